// round 12
// baseline (speedup 1.0000x reference)
#include <cuda_runtime.h>
#include <cuda_fp16.h>
#include <math.h>
#include <stdint.h>

// Problem constants
#define B_   32
#define SEQ_ 577
#define H_   16
#define HD_  88
#define D_   1408
#define IDX_ 24
#define M_   (B_ * SEQ_)   // 18464

// Scratch (device globals)
__device__ __half g_Qh[(size_t)M_ * D_];
__device__ __half g_Kh[(size_t)M_ * D_];
__device__ __half g_Vh[(size_t)M_ * D_];
__device__ __half g_Xh[(size_t)M_ * D_];
__device__ __half g_Wh[4][(size_t)D_ * D_];
__device__ float  g_cos[SEQ_ * 44];
__device__ float  g_sin[SEQ_ * 44];

// ---------------------------------------------------------------------------
// helpers
// ---------------------------------------------------------------------------
__device__ __forceinline__ uint32_t smem_u32(const void* p) {
    uint32_t a;
    asm("{ .reg .u64 t; cvta.to.shared.u64 t, %1; cvt.u32.u64 %0, t; }" : "=r"(a) : "l"(p));
    return a;
}
__device__ __forceinline__ void mma_f16(float* d, const uint32_t* a, const uint32_t* b) {
    asm volatile(
        "mma.sync.aligned.m16n8k16.row.col.f32.f16.f16.f32 "
        "{%0,%1,%2,%3},{%4,%5,%6,%7},{%8,%9},{%0,%1,%2,%3};"
        : "+f"(d[0]), "+f"(d[1]), "+f"(d[2]), "+f"(d[3])
        : "r"(a[0]), "r"(a[1]), "r"(a[2]), "r"(a[3]), "r"(b[0]), "r"(b[1]));
}
__device__ __forceinline__ void ldsm_x4(uint32_t* r, uint32_t addr) {
    asm volatile("ldmatrix.sync.aligned.m8n8.x4.shared.b16 {%0,%1,%2,%3}, [%4];"
                 : "=r"(r[0]), "=r"(r[1]), "=r"(r[2]), "=r"(r[3]) : "r"(addr));
}
__device__ __forceinline__ uint32_t packh2(float lo, float hi) {
    __half2 h = __floats2half2_rn(lo, hi);
    return *(uint32_t*)&h;
}

#define CP_ASYNC(dst, src, sz) \
    asm volatile("cp.async.cg.shared.global [%0], [%1], 16, %2;" \
                 :: "r"(dst), "l"(src), "r"(sz) : "memory")
#define CP_COMMIT() asm volatile("cp.async.commit_group;" ::: "memory")
#define CP_WAIT1()  asm volatile("cp.async.wait_group 1;" ::: "memory")
#define CP_WAIT0()  asm volatile("cp.async.wait_group 0;" ::: "memory")

// ---------------------------------------------------------------------------
// fp32 -> fp16 conversions
// ---------------------------------------------------------------------------
__global__ void f2h_kernel(const float* __restrict__ in,
                           __half* __restrict__ out, int n4)
{
    int i = blockIdx.x * blockDim.x + threadIdx.x;
    if (i >= n4) return;
    float4 v = ((const float4*)in)[i];
    ((__half2*)out)[2 * i]     = __floats2half2_rn(v.x, v.y);
    ((__half2*)out)[2 * i + 1] = __floats2half2_rn(v.z, v.w);
}

__global__ void f2h4_kernel(const float* __restrict__ w0, const float* __restrict__ w1,
                            const float* __restrict__ w2, const float* __restrict__ w3,
                            __half* __restrict__ out, int n4)
{
    int i = blockIdx.x * blockDim.x + threadIdx.x;
    if (i >= n4) return;
    const float* in = (blockIdx.y == 0) ? w0 : (blockIdx.y == 1) ? w1
                     : (blockIdx.y == 2) ? w2 : w3;
    __half* o = out + (size_t)blockIdx.y * D_ * D_;
    float4 v = ((const float4*)in)[i];
    ((__half2*)o)[2 * i]     = __floats2half2_rn(v.x, v.y);
    ((__half2*)o)[2 * i + 1] = __floats2half2_rn(v.z, v.w);
}

// ---------------------------------------------------------------------------
// Rope tables
// ---------------------------------------------------------------------------
__global__ void rope_init_kernel()
{
    int idx = blockIdx.x * blockDim.x + threadIdx.x;
    if (idx >= SEQ_ * 44) return;
    int s = idx / 44, j = idx % 44;
    double f = 0.0;
    if (s != SEQ_ - 1) {
        int fx = s % IDX_, fy = s / IDX_;
        int i = (j < 22) ? j : j - 22;
        double rf = exp((-2.0 * (double)i / 44.0) * log(10000.0));
        double coord = (j < 22) ? (double)(fx + 1) : (double)(fy + 1);
        f = coord * rf;
    }
    g_cos[idx] = (float)cos(f);
    g_sin[idx] = (float)sin(f);
}

// ---------------------------------------------------------------------------
// GEMM tile config
// ---------------------------------------------------------------------------
constexpr int BM = 128, BN = 128, BKH = 64;
constexpr int NKT = D_ / BKH;             // 22
constexpr int ABYTES = BM * 128;          // 16384
constexpr int STG    = 2 * ABYTES;        // 32768
constexpr int GSMEM  = 2 * STG;           // 65536
constexpr int NBN    = D_ / BN;           // 11

// ---------------------------------------------------------------------------
// Epilogue functors
// ---------------------------------------------------------------------------
struct EpiQKV {
    const float* bias;
    __half* C;
    int which;   // 0=Q 1=K 2=V
    int M;
    __device__ __forceinline__ void operator()(int r, int c, float v0, float v1) const {
        if (r >= M) return;
        v0 += bias[c];
        v1 += bias[c + 1];
        if (which < 2) {
            int s = r % SEQ_;
            int j = (c % HD_) >> 1;
            float cs = g_cos[s * 44 + j];
            float sn = g_sin[s * 44 + j];
            float a = v0, b = v1;
            v0 = a * cs - b * sn;
            v1 = a * sn + b * cs;
            if (which == 0) {
                const float qscale = 0.10660035817780521f;
                v0 *= qscale; v1 *= qscale;
            }
        }
        *(__half2*)&C[(size_t)r * D_ + c] = __floats2half2_rn(v0, v1);
    }
};

struct EpiOut {
    const float* bias;
    float* C;
    int M;
    __device__ __forceinline__ void operator()(int r, int c, float v0, float v1) const {
        if (r >= M) return;
        *(float2*)&C[(size_t)r * D_ + c] =
            make_float2(v0 + bias[c], v1 + bias[c + 1]);
    }
};

// Shared GEMM mainloop (one 128x128 tile), ldmatrix fragment feed.
template <typename EPI>
__device__ __forceinline__ void gemm_body(
    const __half* __restrict__ A, const __half* __restrict__ W,
    char* sm, int bm, int bn, int M, EPI epilogue)
{
    const uint32_t sbase = smem_u32(sm);
    const int t = threadIdx.x, lane = t & 31, wid = t >> 5;
    const int g = lane >> 2, tc = lane & 3;
    const int lr = lane & 7, grp = lane >> 3;
    const int warpM = wid & 1;
    const int warpN = wid >> 1;

    uint32_t aoff[4], boff[2];
#pragma unroll
    for (int mt = 0; mt < 4; mt++)
        aoff[mt] = (uint32_t)(warpM * 64 + mt * 16 + lr + ((grp & 1) << 3)) << 7;
#pragma unroll
    for (int np = 0; np < 2; np++)
        boff[np] = (uint32_t)(warpN * 32 + np * 16 + lr + ((grp >> 1) << 3)) << 7;
    const int acpar = grp >> 1;
    const int bcpar = grp & 1;

    float acc[4][4][4];
#pragma unroll
    for (int mt = 0; mt < 4; mt++)
#pragma unroll
        for (int nt = 0; nt < 4; nt++)
#pragma unroll
            for (int i = 0; i < 4; i++) acc[mt][nt][i] = 0.f;

    auto issue = [&](int kt, int stage) {
        const int k0 = kt * BKH;
        uint32_t dA = sbase + stage * STG;
        uint32_t dB = dA + ABYTES;
#pragma unroll
        for (int i = 0; i < 4; i++) {
            int idx = t + 256 * i;
            int row = idx >> 3;
            int c4  = idx & 7;
            uint32_t sw = ((uint32_t)row << 7) + ((uint32_t)(c4 ^ (row & 7)) << 4);
            int gm = bm + row;
            const __half* srcA = A + (size_t)(gm < M ? gm : 0) * D_ + k0 + c4 * 8;
            CP_ASYNC(dA + sw, srcA, (gm < M) ? 16 : 0);
            const __half* srcB = W + (size_t)(bn + row) * D_ + k0 + c4 * 8;
            CP_ASYNC(dB + sw, srcB, 16);
        }
        CP_COMMIT();
    };

    issue(0, 0);
    for (int kt = 0; kt < NKT; kt++) {
        const int buf = kt & 1;
        if (kt + 1 < NKT) { issue(kt + 1, buf ^ 1); CP_WAIT1(); }
        else              { CP_WAIT0(); }
        __syncthreads();

        const uint32_t sA = sbase + buf * STG;
        const uint32_t sB = sA + ABYTES;

#pragma unroll
        for (int ks = 0; ks < 4; ks++) {
            const uint32_t aco = (uint32_t)(((2 * ks + acpar) ^ lr) << 4);
            const uint32_t bco = (uint32_t)(((2 * ks + bcpar) ^ lr) << 4);

            uint32_t af[4][4];
#pragma unroll
            for (int mt = 0; mt < 4; mt++)
                ldsm_x4(af[mt], sA + aoff[mt] + aco);

            uint32_t bf[4][2];
#pragma unroll
            for (int np = 0; np < 2; np++) {
                uint32_t r[4];
                ldsm_x4(r, sB + boff[np] + bco);
                bf[2 * np][0]     = r[0];
                bf[2 * np][1]     = r[1];
                bf[2 * np + 1][0] = r[2];
                bf[2 * np + 1][1] = r[3];
            }
#pragma unroll
            for (int mt = 0; mt < 4; mt++)
#pragma unroll
                for (int nt = 0; nt < 4; nt++)
                    mma_f16(acc[mt][nt], af[mt], bf[nt]);
        }
        __syncthreads();
    }

#pragma unroll
    for (int nt = 0; nt < 4; nt++) {
        int c = bn + warpN * 32 + nt * 8 + tc * 2;
#pragma unroll
        for (int mt = 0; mt < 4; mt++) {
            int r0 = bm + warpM * 64 + mt * 16 + g;
            epilogue(r0,     c, acc[mt][nt][0], acc[mt][nt][1]);
            epilogue(r0 + 8, c, acc[mt][nt][2], acc[mt][nt][3]);
        }
    }
}

// ---------------------------------------------------------------------------
// Fused QKV GEMM + bias + rope (Q scaled). grid.x = 3*NBN.
// ---------------------------------------------------------------------------
__global__ __launch_bounds__(256, 2) void gemm_qkv_kernel(
    const __half* __restrict__ A, const __half* __restrict__ Wall,
    const float* __restrict__ bq, const float* __restrict__ bk,
    const float* __restrict__ bv, __half* __restrict__ Qh,
    __half* __restrict__ Kh, __half* __restrict__ Vh, int M)
{
    extern __shared__ __align__(128) char sm[];
    const int which = blockIdx.x / NBN;
    const int bn = (blockIdx.x % NBN) * BN;
    const int bm = blockIdx.y * BM;

    const __half* W = Wall + (size_t)which * D_ * D_;
    EpiQKV epi;
    epi.bias  = (which == 0) ? bq : (which == 1) ? bk : bv;
    epi.C     = (which == 0) ? Qh : (which == 1) ? Kh : Vh;
    epi.which = which;
    epi.M     = M;

    gemm_body(A, W, sm, bm, bn, M, epi);
}

// ---------------------------------------------------------------------------
// Plain GEMM + bias, fp32 output (final projection)
// ---------------------------------------------------------------------------
__global__ __launch_bounds__(256, 2) void gemm_out_kernel(
    const __half* __restrict__ A, const __half* __restrict__ W,
    const float* __restrict__ bias, float* __restrict__ C, int M)
{
    extern __shared__ __align__(128) char sm[];
    const int bn = blockIdx.x * BN;
    const int bm = blockIdx.y * BM;

    EpiOut epi; epi.bias = bias; epi.C = C; epi.M = M;
    gemm_body(A, W, sm, bm, bn, M, epi);
}

// ---------------------------------------------------------------------------
// Fused flash attention on mma.f16, register-prefetch pipelined staging.
// ---------------------------------------------------------------------------
#define QT   128
#define KT   32
#define QSTR 100
#define VSTR 36

__global__ __launch_bounds__(256) void attn_mma_kernel(
    const __half* __restrict__ Q, const __half* __restrict__ K,
    const __half* __restrict__ V, __half* __restrict__ O)
{
    __shared__ __align__(16) __half Qs[QT * QSTR];
    __shared__ __align__(16) __half Ks[KT * QSTR];
    __shared__ __align__(16) __half Vs[HD_ * VSTR];

    const int qt = blockIdx.x, h = blockIdx.y, b = blockIdx.z;
    const int q0 = qt * QT;
    const int t = threadIdx.x, lane = t & 31, wid = t >> 5;
    const int g = lane >> 2, tc = lane & 3;

    // ---- stage Q tile ----
    for (int idx = t; idx < QT * 24; idx += 256) {
        int r = idx / 24, c = idx % 24;
        int s = q0 + r; if (s >= SEQ_) s = SEQ_ - 1;
        uint2 v = make_uint2(0u, 0u);
        if (c < 22)
            v = *(const uint2*)&Q[(((size_t)b * SEQ_ + s) * H_ + h) * HD_ + c * 4];
        *(uint2*)&Qs[r * QSTR + c * 4] = v;
    }
    __syncthreads();

    const int rw = wid * 16;
    uint32_t qf[6][4];
#pragma unroll
    for (int ks = 0; ks < 6; ks++) {
        const __half* p0 = &Qs[(rw + g) * QSTR + ks * 16 + 2 * tc];
        const __half* p1 = p0 + 8 * QSTR;
        qf[ks][0] = *(const uint32_t*)p0;
        qf[ks][1] = *(const uint32_t*)p1;
        qf[ks][2] = *(const uint32_t*)(p0 + 8);
        qf[ks][3] = *(const uint32_t*)(p1 + 8);
    }

    float oacc[11][4];
#pragma unroll
    for (int nt = 0; nt < 11; nt++)
#pragma unroll
        for (int i = 0; i < 4; i++) oacc[nt][i] = 0.f;
    float m0 = -1e30f, m1 = -1e30f, l0 = 0.f, l1 = 0.f;

    // ---- prefetch registers (K: 3x256 = KT*24 exact; V: KT*22 = 704) ----
    uint2 kpre[3], vpre[3];

    auto prefetch = [&](int k0) {
#pragma unroll
        for (int i = 0; i < 3; i++) {
            int idx = t + 256 * i;
            int r = idx / 24, c = idx % 24;
            int s = k0 + r;
            uint2 v = make_uint2(0u, 0u);
            if (s < SEQ_ && c < 22)
                v = *(const uint2*)&K[(((size_t)b * SEQ_ + s) * H_ + h) * HD_ + c * 4];
            kpre[i] = v;
        }
#pragma unroll
        for (int i = 0; i < 3; i++) {
            int idx = t + 256 * i;
            uint2 v = make_uint2(0u, 0u);
            if (idx < KT * 22) {
                int r = idx / 22, c = idx % 22;
                int s = k0 + r;
                if (s < SEQ_)
                    v = *(const uint2*)&V[(((size_t)b * SEQ_ + s) * H_ + h) * HD_ + c * 4];
            }
            vpre[i] = v;
        }
    };
    auto store_tile = [&]() {
#pragma unroll
        for (int i = 0; i < 3; i++) {
            int idx = t + 256 * i;
            int r = idx / 24, c = idx % 24;
            *(uint2*)&Ks[r * QSTR + c * 4] = kpre[i];
        }
#pragma unroll
        for (int i = 0; i < 3; i++) {
            int idx = t + 256 * i;
            if (idx < KT * 22) {
                int r = idx / 22, c = idx % 22;
                __half h4[4];
                *(uint2*)h4 = vpre[i];
#pragma unroll
                for (int j = 0; j < 4; j++)
                    Vs[(c * 4 + j) * VSTR + r] = h4[j];
            }
        }
    };

    prefetch(0);

    for (int k0 = 0; k0 < SEQ_; k0 += KT) {
        __syncthreads();          // smem free (prev compute / Q hoist done)
        store_tile();
        if (k0 + KT < SEQ_) prefetch(k0 + KT);
        __syncthreads();

        // ---- scores S(16x32) per warp ----
        float sc[4][4];
#pragma unroll
        for (int nt = 0; nt < 4; nt++)
#pragma unroll
            for (int i = 0; i < 4; i++) sc[nt][i] = 0.f;

#pragma unroll
        for (int ks = 0; ks < 6; ks++) {
#pragma unroll
            for (int nt = 0; nt < 4; nt++) {
                const __half* p = &Ks[(nt * 8 + g) * QSTR + ks * 16 + 2 * tc];
                uint32_t bf[2];
                bf[0] = *(const uint32_t*)p;
                bf[1] = *(const uint32_t*)(p + 8);
                mma_f16(sc[nt], qf[ks], bf);
            }
        }

        if (k0 + KT > SEQ_) {
#pragma unroll
            for (int nt = 0; nt < 4; nt++) {
                int kidx = k0 + nt * 8 + 2 * tc;
                if (kidx >= SEQ_)     { sc[nt][0] = -1e30f; sc[nt][2] = -1e30f; }
                if (kidx + 1 >= SEQ_) { sc[nt][1] = -1e30f; sc[nt][3] = -1e30f; }
            }
        }

        // ---- online softmax (warp-local) ----
        float mx0 = sc[0][0], mx1 = sc[0][2];
#pragma unroll
        for (int nt = 0; nt < 4; nt++) {
            mx0 = fmaxf(mx0, fmaxf(sc[nt][0], sc[nt][1]));
            mx1 = fmaxf(mx1, fmaxf(sc[nt][2], sc[nt][3]));
        }
        mx0 = fmaxf(mx0, __shfl_xor_sync(0xffffffffu, mx0, 1));
        mx0 = fmaxf(mx0, __shfl_xor_sync(0xffffffffu, mx0, 2));
        mx1 = fmaxf(mx1, __shfl_xor_sync(0xffffffffu, mx1, 1));
        mx1 = fmaxf(mx1, __shfl_xor_sync(0xffffffffu, mx1, 2));
        mx0 = fmaxf(mx0, m0); mx1 = fmaxf(mx1, m1);
        float corr0 = __expf(m0 - mx0), corr1 = __expf(m1 - mx1);
        m0 = mx0; m1 = mx1;

        float s0 = 0.f, s1 = 0.f;
#pragma unroll
        for (int nt = 0; nt < 4; nt++) {
            sc[nt][0] = __expf(sc[nt][0] - m0);
            sc[nt][1] = __expf(sc[nt][1] - m0);
            sc[nt][2] = __expf(sc[nt][2] - m1);
            sc[nt][3] = __expf(sc[nt][3] - m1);
            s0 += sc[nt][0] + sc[nt][1];
            s1 += sc[nt][2] + sc[nt][3];
        }
        s0 += __shfl_xor_sync(0xffffffffu, s0, 1);
        s0 += __shfl_xor_sync(0xffffffffu, s0, 2);
        s1 += __shfl_xor_sync(0xffffffffu, s1, 1);
        s1 += __shfl_xor_sync(0xffffffffu, s1, 2);
        l0 = l0 * corr0 + s0;
        l1 = l1 * corr1 + s1;

#pragma unroll
        for (int nt = 0; nt < 11; nt++) {
            oacc[nt][0] *= corr0; oacc[nt][1] *= corr0;
            oacc[nt][2] *= corr1; oacc[nt][3] *= corr1;
        }

        uint32_t pf[2][4];
#pragma unroll
        for (int kv = 0; kv < 2; kv++) {
            pf[kv][0] = packh2(sc[2 * kv][0],     sc[2 * kv][1]);
            pf[kv][1] = packh2(sc[2 * kv][2],     sc[2 * kv][3]);
            pf[kv][2] = packh2(sc[2 * kv + 1][0], sc[2 * kv + 1][1]);
            pf[kv][3] = packh2(sc[2 * kv + 1][2], sc[2 * kv + 1][3]);
        }

#pragma unroll
        for (int kv = 0; kv < 2; kv++) {
#pragma unroll
            for (int nt = 0; nt < 11; nt++) {
                const __half* p = &Vs[(nt * 8 + g) * VSTR + kv * 16 + 2 * tc];
                uint32_t bf[2];
                bf[0] = *(const uint32_t*)p;
                bf[1] = *(const uint32_t*)(p + 8);
                mma_f16(oacc[nt], pf[kv], bf);
            }
        }
    }

    float inv0 = 1.f / l0, inv1 = 1.f / l1;
    int s0 = q0 + rw + g, s1 = s0 + 8;
#pragma unroll
    for (int nt = 0; nt < 11; nt++) {
        int d = nt * 8 + 2 * tc;
        if (s0 < SEQ_)
            *(__half2*)&O[(((size_t)b * SEQ_ + s0) * H_ + h) * HD_ + d] =
                __floats2half2_rn(oacc[nt][0] * inv0, oacc[nt][1] * inv0);
        if (s1 < SEQ_)
            *(__half2*)&O[(((size_t)b * SEQ_ + s1) * H_ + h) * HD_ + d] =
                __floats2half2_rn(oacc[nt][2] * inv1, oacc[nt][3] * inv1);
    }
}

// ---------------------------------------------------------------------------
extern "C" void kernel_launch(void* const* d_in, const int* in_sizes, int n_in,
                              void* d_out, int out_size)
{
    const float* X  = (const float*)d_in[0];
    const float* wq = (const float*)d_in[1];
    const float* bq = (const float*)d_in[2];
    const float* wk = (const float*)d_in[3];
    const float* bk = (const float*)d_in[4];
    const float* wv = (const float*)d_in[5];
    const float* bv = (const float*)d_in[6];
    const float* wo = (const float*)d_in[7];
    const float* bo = (const float*)d_in[8];
    float* out = (float*)d_out;

    __half *Qh, *Kh, *Vh, *Xh, *Wh;
    cudaGetSymbolAddress((void**)&Qh, g_Qh);
    cudaGetSymbolAddress((void**)&Kh, g_Kh);
    cudaGetSymbolAddress((void**)&Vh, g_Vh);
    cudaGetSymbolAddress((void**)&Xh, g_Xh);
    cudaGetSymbolAddress((void**)&Wh, g_Wh);

    cudaFuncSetAttribute(gemm_qkv_kernel,
                         cudaFuncAttributeMaxDynamicSharedMemorySize, GSMEM);
    cudaFuncSetAttribute(gemm_out_kernel,
                         cudaFuncAttributeMaxDynamicSharedMemorySize, GSMEM);

    const int WN4 = D_ * D_ / 4;
    const int XN4 = M_ * D_ / 4;
    f2h_kernel<<<(XN4 + 255) / 256, 256>>>(X, Xh, XN4);
    dim3 wgrid((WN4 + 255) / 256, 4);
    f2h4_kernel<<<wgrid, 256>>>(wq, wk, wv, wo, Wh, WN4);
    rope_init_kernel<<<(SEQ_ * 44 + 255) / 256, 256>>>();

    dim3 qgrid(3 * NBN, (M_ + BM - 1) / BM);   // (33, 145)
    gemm_qkv_kernel<<<qgrid, 256, GSMEM>>>(Xh, Wh, bq, bk, bv, Qh, Kh, Vh, M_);

    dim3 agrid((SEQ_ + QT - 1) / QT, H_, B_);  // (5, 16, 32)
    attn_mma_kernel<<<agrid, 256>>>(Qh, Kh, Vh, Xh);

    dim3 ogrid(NBN, (M_ + BM - 1) / BM);       // (11, 145)
    gemm_out_kernel<<<ogrid, 256, GSMEM>>>(Xh, Wh + 3 * (size_t)D_ * D_, bo, out, M_);
}

// round 13
// speedup vs baseline: 1.0084x; 1.0084x over previous
#include <cuda_runtime.h>
#include <cuda_fp16.h>
#include <math.h>
#include <stdint.h>

// Problem constants
#define B_   32
#define SEQ_ 577
#define H_   16
#define HD_  88
#define D_   1408
#define IDX_ 24
#define M_   (B_ * SEQ_)   // 18464

// Scratch (device globals)
__device__ __half g_Qh[(size_t)M_ * D_];
__device__ __half g_Kh[(size_t)M_ * D_];
__device__ __half g_Vh[(size_t)M_ * D_];
__device__ __half g_Xh[(size_t)M_ * D_];
__device__ __half g_Wh[4][(size_t)D_ * D_];
__device__ float  g_cos[SEQ_ * 44];
__device__ float  g_sin[SEQ_ * 44];

// ---------------------------------------------------------------------------
// helpers
// ---------------------------------------------------------------------------
__device__ __forceinline__ uint32_t smem_u32(const void* p) {
    uint32_t a;
    asm("{ .reg .u64 t; cvta.to.shared.u64 t, %1; cvt.u32.u64 %0, t; }" : "=r"(a) : "l"(p));
    return a;
}
__device__ __forceinline__ void mma_f16(float* d, const uint32_t* a, const uint32_t* b) {
    asm volatile(
        "mma.sync.aligned.m16n8k16.row.col.f32.f16.f16.f32 "
        "{%0,%1,%2,%3},{%4,%5,%6,%7},{%8,%9},{%0,%1,%2,%3};"
        : "+f"(d[0]), "+f"(d[1]), "+f"(d[2]), "+f"(d[3])
        : "r"(a[0]), "r"(a[1]), "r"(a[2]), "r"(a[3]), "r"(b[0]), "r"(b[1]));
}
__device__ __forceinline__ void ldsm_x4(uint32_t* r, uint32_t addr) {
    asm volatile("ldmatrix.sync.aligned.m8n8.x4.shared.b16 {%0,%1,%2,%3}, [%4];"
                 : "=r"(r[0]), "=r"(r[1]), "=r"(r[2]), "=r"(r[3]) : "r"(addr));
}
__device__ __forceinline__ uint32_t packh2(float lo, float hi) {
    __half2 h = __floats2half2_rn(lo, hi);
    return *(uint32_t*)&h;
}

#define CP_ASYNC(dst, src, sz) \
    asm volatile("cp.async.cg.shared.global [%0], [%1], 16, %2;" \
                 :: "r"(dst), "l"(src), "r"(sz) : "memory")
#define CP_COMMIT() asm volatile("cp.async.commit_group;" ::: "memory")
#define CP_WAIT1()  asm volatile("cp.async.wait_group 1;" ::: "memory")
#define CP_WAIT0()  asm volatile("cp.async.wait_group 0;" ::: "memory")

// ---------------------------------------------------------------------------
// fp32 -> fp16 conversions
// ---------------------------------------------------------------------------
__global__ void f2h_kernel(const float* __restrict__ in,
                           __half* __restrict__ out, int n4)
{
    int i = blockIdx.x * blockDim.x + threadIdx.x;
    if (i >= n4) return;
    float4 v = ((const float4*)in)[i];
    ((__half2*)out)[2 * i]     = __floats2half2_rn(v.x, v.y);
    ((__half2*)out)[2 * i + 1] = __floats2half2_rn(v.z, v.w);
}

__global__ void f2h4_kernel(const float* __restrict__ w0, const float* __restrict__ w1,
                            const float* __restrict__ w2, const float* __restrict__ w3,
                            __half* __restrict__ out, int n4)
{
    int i = blockIdx.x * blockDim.x + threadIdx.x;
    if (i >= n4) return;
    const float* in = (blockIdx.y == 0) ? w0 : (blockIdx.y == 1) ? w1
                     : (blockIdx.y == 2) ? w2 : w3;
    __half* o = out + (size_t)blockIdx.y * D_ * D_;
    float4 v = ((const float4*)in)[i];
    ((__half2*)o)[2 * i]     = __floats2half2_rn(v.x, v.y);
    ((__half2*)o)[2 * i + 1] = __floats2half2_rn(v.z, v.w);
}

// ---------------------------------------------------------------------------
// Rope tables
// ---------------------------------------------------------------------------
__global__ void rope_init_kernel()
{
    int idx = blockIdx.x * blockDim.x + threadIdx.x;
    if (idx >= SEQ_ * 44) return;
    int s = idx / 44, j = idx % 44;
    double f = 0.0;
    if (s != SEQ_ - 1) {
        int fx = s % IDX_, fy = s / IDX_;
        int i = (j < 22) ? j : j - 22;
        double rf = exp((-2.0 * (double)i / 44.0) * log(10000.0));
        double coord = (j < 22) ? (double)(fx + 1) : (double)(fy + 1);
        f = coord * rf;
    }
    g_cos[idx] = (float)cos(f);
    g_sin[idx] = (float)sin(f);
}

// ---------------------------------------------------------------------------
// GEMM tile config — 3-stage cp.async pipeline, one barrier per K-tile
// ---------------------------------------------------------------------------
constexpr int BM = 128, BN = 128, BKH = 64;
constexpr int NKT = D_ / BKH;             // 22
constexpr int ABYTES = BM * 128;          // 16384
constexpr int STG    = 2 * ABYTES;        // 32768 per stage (A+B)
constexpr int NSTAGE = 3;
constexpr int GSMEM  = NSTAGE * STG;      // 98304
constexpr int NBN    = D_ / BN;           // 11

// ---------------------------------------------------------------------------
// Epilogue functors
// ---------------------------------------------------------------------------
struct EpiQKV {
    const float* bias;
    __half* C;
    int which;   // 0=Q 1=K 2=V
    int M;
    __device__ __forceinline__ void operator()(int r, int c, float v0, float v1) const {
        if (r >= M) return;
        v0 += bias[c];
        v1 += bias[c + 1];
        if (which < 2) {
            int s = r % SEQ_;
            int j = (c % HD_) >> 1;
            float cs = g_cos[s * 44 + j];
            float sn = g_sin[s * 44 + j];
            float a = v0, b = v1;
            v0 = a * cs - b * sn;
            v1 = a * sn + b * cs;
            if (which == 0) {
                const float qscale = 0.10660035817780521f;
                v0 *= qscale; v1 *= qscale;
            }
        }
        *(__half2*)&C[(size_t)r * D_ + c] = __floats2half2_rn(v0, v1);
    }
};

struct EpiOut {
    const float* bias;
    float* C;
    int M;
    __device__ __forceinline__ void operator()(int r, int c, float v0, float v1) const {
        if (r >= M) return;
        *(float2*)&C[(size_t)r * D_ + c] =
            make_float2(v0 + bias[c], v1 + bias[c + 1]);
    }
};

// Shared GEMM mainloop (one 128x128 tile), ldmatrix feed, 3-stage pipeline.
template <typename EPI>
__device__ __forceinline__ void gemm_body(
    const __half* __restrict__ A, const __half* __restrict__ W,
    char* sm, int bm, int bn, int M, EPI epilogue)
{
    const uint32_t sbase = smem_u32(sm);
    const int t = threadIdx.x, lane = t & 31, wid = t >> 5;
    const int g = lane >> 2, tc = lane & 3;
    const int lr = lane & 7, grp = lane >> 3;
    const int warpM = wid & 1;
    const int warpN = wid >> 1;

    uint32_t aoff[4], boff[2];
#pragma unroll
    for (int mt = 0; mt < 4; mt++)
        aoff[mt] = (uint32_t)(warpM * 64 + mt * 16 + lr + ((grp & 1) << 3)) << 7;
#pragma unroll
    for (int np = 0; np < 2; np++)
        boff[np] = (uint32_t)(warpN * 32 + np * 16 + lr + ((grp >> 1) << 3)) << 7;
    const int acpar = grp >> 1;
    const int bcpar = grp & 1;

    float acc[4][4][4];
#pragma unroll
    for (int mt = 0; mt < 4; mt++)
#pragma unroll
        for (int nt = 0; nt < 4; nt++)
#pragma unroll
            for (int i = 0; i < 4; i++) acc[mt][nt][i] = 0.f;

    auto issue = [&](int kt, int stage) {
        const int k0 = kt * BKH;
        uint32_t dA = sbase + stage * STG;
        uint32_t dB = dA + ABYTES;
#pragma unroll
        for (int i = 0; i < 4; i++) {
            int idx = t + 256 * i;
            int row = idx >> 3;
            int c4  = idx & 7;
            uint32_t sw = ((uint32_t)row << 7) + ((uint32_t)(c4 ^ (row & 7)) << 4);
            int gm = bm + row;
            const __half* srcA = A + (size_t)(gm < M ? gm : 0) * D_ + k0 + c4 * 8;
            CP_ASYNC(dA + sw, srcA, (gm < M) ? 16 : 0);
            const __half* srcB = W + (size_t)(bn + row) * D_ + k0 + c4 * 8;
            CP_ASYNC(dB + sw, srcB, 16);
        }
        CP_COMMIT();
    };

    // Prologue: 2 tiles in flight
    issue(0, 0);
    issue(1, 1);

    int stage = 0;
    for (int kt = 0; kt < NKT; kt++) {
        CP_WAIT1();            // tile kt resident (<=1 pending: tile kt+1)
        __syncthreads();       // visibility + buffer-reuse protection

        if (kt + 2 < NKT) issue(kt + 2, (stage + 2) % NSTAGE);

        const uint32_t sA = sbase + stage * STG;
        const uint32_t sB = sA + ABYTES;

#pragma unroll
        for (int ks = 0; ks < 4; ks++) {
            const uint32_t aco = (uint32_t)(((2 * ks + acpar) ^ lr) << 4);
            const uint32_t bco = (uint32_t)(((2 * ks + bcpar) ^ lr) << 4);

            uint32_t af[4][4];
#pragma unroll
            for (int mt = 0; mt < 4; mt++)
                ldsm_x4(af[mt], sA + aoff[mt] + aco);

            uint32_t bf[4][2];
#pragma unroll
            for (int np = 0; np < 2; np++) {
                uint32_t r[4];
                ldsm_x4(r, sB + boff[np] + bco);
                bf[2 * np][0]     = r[0];
                bf[2 * np][1]     = r[1];
                bf[2 * np + 1][0] = r[2];
                bf[2 * np + 1][1] = r[3];
            }
#pragma unroll
            for (int mt = 0; mt < 4; mt++)
#pragma unroll
                for (int nt = 0; nt < 4; nt++)
                    mma_f16(acc[mt][nt], af[mt], bf[nt]);
        }
        stage = (stage + 1) % NSTAGE;
    }

#pragma unroll
    for (int nt = 0; nt < 4; nt++) {
        int c = bn + warpN * 32 + nt * 8 + tc * 2;
#pragma unroll
        for (int mt = 0; mt < 4; mt++) {
            int r0 = bm + warpM * 64 + mt * 16 + g;
            epilogue(r0,     c, acc[mt][nt][0], acc[mt][nt][1]);
            epilogue(r0 + 8, c, acc[mt][nt][2], acc[mt][nt][3]);
        }
    }
}

// ---------------------------------------------------------------------------
// Fused QKV GEMM + bias + rope (Q scaled). grid.x = 3*NBN.
// ---------------------------------------------------------------------------
__global__ __launch_bounds__(256, 2) void gemm_qkv_kernel(
    const __half* __restrict__ A, const __half* __restrict__ Wall,
    const float* __restrict__ bq, const float* __restrict__ bk,
    const float* __restrict__ bv, __half* __restrict__ Qh,
    __half* __restrict__ Kh, __half* __restrict__ Vh, int M)
{
    extern __shared__ __align__(128) char sm[];
    const int which = blockIdx.x / NBN;
    const int bn = (blockIdx.x % NBN) * BN;
    const int bm = blockIdx.y * BM;

    const __half* W = Wall + (size_t)which * D_ * D_;
    EpiQKV epi;
    epi.bias  = (which == 0) ? bq : (which == 1) ? bk : bv;
    epi.C     = (which == 0) ? Qh : (which == 1) ? Kh : Vh;
    epi.which = which;
    epi.M     = M;

    gemm_body(A, W, sm, bm, bn, M, epi);
}

// ---------------------------------------------------------------------------
// Plain GEMM + bias, fp32 output (final projection)
// ---------------------------------------------------------------------------
__global__ __launch_bounds__(256, 2) void gemm_out_kernel(
    const __half* __restrict__ A, const __half* __restrict__ W,
    const float* __restrict__ bias, float* __restrict__ C, int M)
{
    extern __shared__ __align__(128) char sm[];
    const int bn = blockIdx.x * BN;
    const int bm = blockIdx.y * BM;

    EpiOut epi; epi.bias = bias; epi.C = C; epi.M = M;
    gemm_body(A, W, sm, bm, bn, M, epi);
}

// ---------------------------------------------------------------------------
// Fused flash attention on mma.f16 — reverted to the proven R11 version.
// ---------------------------------------------------------------------------
#define QT   128
#define KT   32
#define QSTR 100
#define VSTR 36

__global__ __launch_bounds__(256) void attn_mma_kernel(
    const __half* __restrict__ Q, const __half* __restrict__ K,
    const __half* __restrict__ V, __half* __restrict__ O)
{
    __shared__ __align__(16) __half Qs[QT * QSTR];
    __shared__ __align__(16) __half Ks[KT * QSTR];
    __shared__ __align__(16) __half Vs[HD_ * VSTR];

    const int qt = blockIdx.x, h = blockIdx.y, b = blockIdx.z;
    const int q0 = qt * QT;
    const int t = threadIdx.x, lane = t & 31, wid = t >> 5;
    const int g = lane >> 2, tc = lane & 3;

    for (int idx = t; idx < QT * 24; idx += 256) {
        int r = idx / 24, c = idx % 24;
        int s = q0 + r; if (s >= SEQ_) s = SEQ_ - 1;
        uint2 v = make_uint2(0u, 0u);
        if (c < 22)
            v = *(const uint2*)&Q[(((size_t)b * SEQ_ + s) * H_ + h) * HD_ + c * 4];
        *(uint2*)&Qs[r * QSTR + c * 4] = v;
    }
    __syncthreads();

    const int rw = wid * 16;
    uint32_t qf[6][4];
#pragma unroll
    for (int ks = 0; ks < 6; ks++) {
        const __half* p0 = &Qs[(rw + g) * QSTR + ks * 16 + 2 * tc];
        const __half* p1 = p0 + 8 * QSTR;
        qf[ks][0] = *(const uint32_t*)p0;
        qf[ks][1] = *(const uint32_t*)p1;
        qf[ks][2] = *(const uint32_t*)(p0 + 8);
        qf[ks][3] = *(const uint32_t*)(p1 + 8);
    }
    __syncthreads();

    float oacc[11][4];
#pragma unroll
    for (int nt = 0; nt < 11; nt++)
#pragma unroll
        for (int i = 0; i < 4; i++) oacc[nt][i] = 0.f;
    float m0 = -1e30f, m1 = -1e30f, l0 = 0.f, l1 = 0.f;

    for (int k0 = 0; k0 < SEQ_; k0 += KT) {
        for (int idx = t; idx < KT * 24; idx += 256) {
            int r = idx / 24, c = idx % 24;
            int s = k0 + r;
            uint2 v = make_uint2(0u, 0u);
            if (s < SEQ_ && c < 22)
                v = *(const uint2*)&K[(((size_t)b * SEQ_ + s) * H_ + h) * HD_ + c * 4];
            *(uint2*)&Ks[r * QSTR + c * 4] = v;
        }
        for (int idx = t; idx < KT * 22; idx += 256) {
            int r = idx / 22, c = idx % 22;
            int s = k0 + r;
            uint2 v = make_uint2(0u, 0u);
            if (s < SEQ_)
                v = *(const uint2*)&V[(((size_t)b * SEQ_ + s) * H_ + h) * HD_ + c * 4];
            __half h4[4];
            *(uint2*)h4 = v;
#pragma unroll
            for (int j = 0; j < 4; j++)
                Vs[(c * 4 + j) * VSTR + r] = h4[j];
        }
        __syncthreads();

        float sc[4][4];
#pragma unroll
        for (int nt = 0; nt < 4; nt++)
#pragma unroll
            for (int i = 0; i < 4; i++) sc[nt][i] = 0.f;

#pragma unroll
        for (int ks = 0; ks < 6; ks++) {
#pragma unroll
            for (int nt = 0; nt < 4; nt++) {
                const __half* p = &Ks[(nt * 8 + g) * QSTR + ks * 16 + 2 * tc];
                uint32_t bf[2];
                bf[0] = *(const uint32_t*)p;
                bf[1] = *(const uint32_t*)(p + 8);
                mma_f16(sc[nt], qf[ks], bf);
            }
        }

        if (k0 + KT > SEQ_) {
#pragma unroll
            for (int nt = 0; nt < 4; nt++) {
                int kidx = k0 + nt * 8 + 2 * tc;
                if (kidx >= SEQ_)     { sc[nt][0] = -1e30f; sc[nt][2] = -1e30f; }
                if (kidx + 1 >= SEQ_) { sc[nt][1] = -1e30f; sc[nt][3] = -1e30f; }
            }
        }

        float mx0 = sc[0][0], mx1 = sc[0][2];
#pragma unroll
        for (int nt = 0; nt < 4; nt++) {
            mx0 = fmaxf(mx0, fmaxf(sc[nt][0], sc[nt][1]));
            mx1 = fmaxf(mx1, fmaxf(sc[nt][2], sc[nt][3]));
        }
        mx0 = fmaxf(mx0, __shfl_xor_sync(0xffffffffu, mx0, 1));
        mx0 = fmaxf(mx0, __shfl_xor_sync(0xffffffffu, mx0, 2));
        mx1 = fmaxf(mx1, __shfl_xor_sync(0xffffffffu, mx1, 1));
        mx1 = fmaxf(mx1, __shfl_xor_sync(0xffffffffu, mx1, 2));
        mx0 = fmaxf(mx0, m0); mx1 = fmaxf(mx1, m1);
        float corr0 = __expf(m0 - mx0), corr1 = __expf(m1 - mx1);
        m0 = mx0; m1 = mx1;

        float s0 = 0.f, s1 = 0.f;
#pragma unroll
        for (int nt = 0; nt < 4; nt++) {
            sc[nt][0] = __expf(sc[nt][0] - m0);
            sc[nt][1] = __expf(sc[nt][1] - m0);
            sc[nt][2] = __expf(sc[nt][2] - m1);
            sc[nt][3] = __expf(sc[nt][3] - m1);
            s0 += sc[nt][0] + sc[nt][1];
            s1 += sc[nt][2] + sc[nt][3];
        }
        s0 += __shfl_xor_sync(0xffffffffu, s0, 1);
        s0 += __shfl_xor_sync(0xffffffffu, s0, 2);
        s1 += __shfl_xor_sync(0xffffffffu, s1, 1);
        s1 += __shfl_xor_sync(0xffffffffu, s1, 2);
        l0 = l0 * corr0 + s0;
        l1 = l1 * corr1 + s1;

#pragma unroll
        for (int nt = 0; nt < 11; nt++) {
            oacc[nt][0] *= corr0; oacc[nt][1] *= corr0;
            oacc[nt][2] *= corr1; oacc[nt][3] *= corr1;
        }

        uint32_t pf[2][4];
#pragma unroll
        for (int kv = 0; kv < 2; kv++) {
            pf[kv][0] = packh2(sc[2 * kv][0],     sc[2 * kv][1]);
            pf[kv][1] = packh2(sc[2 * kv][2],     sc[2 * kv][3]);
            pf[kv][2] = packh2(sc[2 * kv + 1][0], sc[2 * kv + 1][1]);
            pf[kv][3] = packh2(sc[2 * kv + 1][2], sc[2 * kv + 1][3]);
        }

#pragma unroll
        for (int kv = 0; kv < 2; kv++) {
#pragma unroll
            for (int nt = 0; nt < 11; nt++) {
                const __half* p = &Vs[(nt * 8 + g) * VSTR + kv * 16 + 2 * tc];
                uint32_t bf[2];
                bf[0] = *(const uint32_t*)p;
                bf[1] = *(const uint32_t*)(p + 8);
                mma_f16(oacc[nt], pf[kv], bf);
            }
        }
        __syncthreads();
    }

    float inv0 = 1.f / l0, inv1 = 1.f / l1;
    int s0 = q0 + rw + g, s1 = s0 + 8;
#pragma unroll
    for (int nt = 0; nt < 11; nt++) {
        int d = nt * 8 + 2 * tc;
        if (s0 < SEQ_)
            *(__half2*)&O[(((size_t)b * SEQ_ + s0) * H_ + h) * HD_ + d] =
                __floats2half2_rn(oacc[nt][0] * inv0, oacc[nt][1] * inv0);
        if (s1 < SEQ_)
            *(__half2*)&O[(((size_t)b * SEQ_ + s1) * H_ + h) * HD_ + d] =
                __floats2half2_rn(oacc[nt][2] * inv1, oacc[nt][3] * inv1);
    }
}

// ---------------------------------------------------------------------------
extern "C" void kernel_launch(void* const* d_in, const int* in_sizes, int n_in,
                              void* d_out, int out_size)
{
    const float* X  = (const float*)d_in[0];
    const float* wq = (const float*)d_in[1];
    const float* bq = (const float*)d_in[2];
    const float* wk = (const float*)d_in[3];
    const float* bk = (const float*)d_in[4];
    const float* wv = (const float*)d_in[5];
    const float* bv = (const float*)d_in[6];
    const float* wo = (const float*)d_in[7];
    const float* bo = (const float*)d_in[8];
    float* out = (float*)d_out;

    __half *Qh, *Kh, *Vh, *Xh, *Wh;
    cudaGetSymbolAddress((void**)&Qh, g_Qh);
    cudaGetSymbolAddress((void**)&Kh, g_Kh);
    cudaGetSymbolAddress((void**)&Vh, g_Vh);
    cudaGetSymbolAddress((void**)&Xh, g_Xh);
    cudaGetSymbolAddress((void**)&Wh, g_Wh);

    cudaFuncSetAttribute(gemm_qkv_kernel,
                         cudaFuncAttributeMaxDynamicSharedMemorySize, GSMEM);
    cudaFuncSetAttribute(gemm_out_kernel,
                         cudaFuncAttributeMaxDynamicSharedMemorySize, GSMEM);

    const int WN4 = D_ * D_ / 4;
    const int XN4 = M_ * D_ / 4;
    f2h_kernel<<<(XN4 + 255) / 256, 256>>>(X, Xh, XN4);
    dim3 wgrid((WN4 + 255) / 256, 4);
    f2h4_kernel<<<wgrid, 256>>>(wq, wk, wv, wo, Wh, WN4);
    rope_init_kernel<<<(SEQ_ * 44 + 255) / 256, 256>>>();

    dim3 qgrid(3 * NBN, (M_ + BM - 1) / BM);   // (33, 145)
    gemm_qkv_kernel<<<qgrid, 256, GSMEM>>>(Xh, Wh, bq, bk, bv, Qh, Kh, Vh, M_);

    dim3 agrid((SEQ_ + QT - 1) / QT, H_, B_);  // (5, 16, 32)
    attn_mma_kernel<<<agrid, 256>>>(Qh, Kh, Vh, Xh);

    dim3 ogrid(NBN, (M_ + BM - 1) / BM);       // (11, 145)
    gemm_out_kernel<<<ogrid, 256, GSMEM>>>(Xh, Wh + 3 * (size_t)D_ * D_, bo, out, M_);
}

// round 14
// speedup vs baseline: 1.0382x; 1.0295x over previous
#include <cuda_runtime.h>
#include <cuda_fp16.h>
#include <math.h>
#include <stdint.h>

// Problem constants
#define B_   32
#define SEQ_ 577
#define H_   16
#define HD_  88
#define D_   1408
#define IDX_ 24
#define M_   (B_ * SEQ_)   // 18464

// Scratch (device globals)
__device__ __half g_Qh[(size_t)M_ * D_];
__device__ __half g_Kh[(size_t)M_ * D_];
__device__ __half g_Vh[(size_t)M_ * D_];
__device__ __half g_Xh[(size_t)M_ * D_];
__device__ __half g_Wh[4][(size_t)D_ * D_];
__device__ float  g_cos[SEQ_ * 44];
__device__ float  g_sin[SEQ_ * 44];

// ---------------------------------------------------------------------------
// helpers
// ---------------------------------------------------------------------------
__device__ __forceinline__ uint32_t smem_u32(const void* p) {
    uint32_t a;
    asm("{ .reg .u64 t; cvta.to.shared.u64 t, %1; cvt.u32.u64 %0, t; }" : "=r"(a) : "l"(p));
    return a;
}
__device__ __forceinline__ void mma_f16(float* d, const uint32_t* a, const uint32_t* b) {
    asm volatile(
        "mma.sync.aligned.m16n8k16.row.col.f32.f16.f16.f32 "
        "{%0,%1,%2,%3},{%4,%5,%6,%7},{%8,%9},{%0,%1,%2,%3};"
        : "+f"(d[0]), "+f"(d[1]), "+f"(d[2]), "+f"(d[3])
        : "r"(a[0]), "r"(a[1]), "r"(a[2]), "r"(a[3]), "r"(b[0]), "r"(b[1]));
}
__device__ __forceinline__ void ldsm_x4(uint32_t* r, uint32_t addr) {
    asm volatile("ldmatrix.sync.aligned.m8n8.x4.shared.b16 {%0,%1,%2,%3}, [%4];"
                 : "=r"(r[0]), "=r"(r[1]), "=r"(r[2]), "=r"(r[3]) : "r"(addr));
}
__device__ __forceinline__ uint32_t packh2(float lo, float hi) {
    __half2 h = __floats2half2_rn(lo, hi);
    return *(uint32_t*)&h;
}

#define CP_ASYNC(dst, src, sz) \
    asm volatile("cp.async.cg.shared.global [%0], [%1], 16, %2;" \
                 :: "r"(dst), "l"(src), "r"(sz) : "memory")
#define CP_COMMIT() asm volatile("cp.async.commit_group;" ::: "memory")
#define CP_WAIT1()  asm volatile("cp.async.wait_group 1;" ::: "memory")
#define CP_WAIT0()  asm volatile("cp.async.wait_group 0;" ::: "memory")

// ---------------------------------------------------------------------------
// fp32 -> fp16 conversions
// ---------------------------------------------------------------------------
__global__ void f2h_kernel(const float* __restrict__ in,
                           __half* __restrict__ out, int n4)
{
    int i = blockIdx.x * blockDim.x + threadIdx.x;
    if (i >= n4) return;
    float4 v = ((const float4*)in)[i];
    ((__half2*)out)[2 * i]     = __floats2half2_rn(v.x, v.y);
    ((__half2*)out)[2 * i + 1] = __floats2half2_rn(v.z, v.w);
}

__global__ void f2h4_kernel(const float* __restrict__ w0, const float* __restrict__ w1,
                            const float* __restrict__ w2, const float* __restrict__ w3,
                            __half* __restrict__ out, int n4)
{
    int i = blockIdx.x * blockDim.x + threadIdx.x;
    if (i >= n4) return;
    const float* in = (blockIdx.y == 0) ? w0 : (blockIdx.y == 1) ? w1
                     : (blockIdx.y == 2) ? w2 : w3;
    __half* o = out + (size_t)blockIdx.y * D_ * D_;
    float4 v = ((const float4*)in)[i];
    ((__half2*)o)[2 * i]     = __floats2half2_rn(v.x, v.y);
    ((__half2*)o)[2 * i + 1] = __floats2half2_rn(v.z, v.w);
}

// ---------------------------------------------------------------------------
// Rope tables
// ---------------------------------------------------------------------------
__global__ void rope_init_kernel()
{
    int idx = blockIdx.x * blockDim.x + threadIdx.x;
    if (idx >= SEQ_ * 44) return;
    int s = idx / 44, j = idx % 44;
    double f = 0.0;
    if (s != SEQ_ - 1) {
        int fx = s % IDX_, fy = s / IDX_;
        int i = (j < 22) ? j : j - 22;
        double rf = exp((-2.0 * (double)i / 44.0) * log(10000.0));
        double coord = (j < 22) ? (double)(fx + 1) : (double)(fy + 1);
        f = coord * rf;
    }
    g_cos[idx] = (float)cos(f);
    g_sin[idx] = (float)sin(f);
}

// ---------------------------------------------------------------------------
// GEMM tile config — R11 2-stage pipeline (proven fastest)
// ---------------------------------------------------------------------------
constexpr int BM = 128, BN = 128, BKH = 64;
constexpr int NKT = D_ / BKH;             // 22
constexpr int ABYTES = BM * 128;          // 16384
constexpr int STG    = 2 * ABYTES;        // 32768
constexpr int GSMEM  = 2 * STG;           // 65536
constexpr int NBN    = D_ / BN;           // 11

// ---------------------------------------------------------------------------
// Epilogue functors
// ---------------------------------------------------------------------------
struct EpiQKV {
    const float* bias;
    __half* C;
    int which;   // 0=Q 1=K 2=V
    int M;
    __device__ __forceinline__ void operator()(int r, int c, float v0, float v1) const {
        if (r >= M) return;
        v0 += bias[c];
        v1 += bias[c + 1];
        if (which < 2) {
            int s = r % SEQ_;
            int j = (c % HD_) >> 1;
            float cs = g_cos[s * 44 + j];
            float sn = g_sin[s * 44 + j];
            float a = v0, b = v1;
            v0 = a * cs - b * sn;
            v1 = a * sn + b * cs;
            if (which == 0) {
                const float qscale = 0.10660035817780521f;
                v0 *= qscale; v1 *= qscale;
            }
        }
        *(__half2*)&C[(size_t)r * D_ + c] = __floats2half2_rn(v0, v1);
    }
};

struct EpiOut {
    const float* bias;
    float* C;
    int M;
    __device__ __forceinline__ void operator()(int r, int c, float v0, float v1) const {
        if (r >= M) return;
        *(float2*)&C[(size_t)r * D_ + c] =
            make_float2(v0 + bias[c], v1 + bias[c + 1]);
    }
};

// Shared GEMM mainloop (one 128x128 tile), ldmatrix feed, 2-stage pipeline.
template <typename EPI>
__device__ __forceinline__ void gemm_body(
    const __half* __restrict__ A, const __half* __restrict__ W,
    char* sm, int bm, int bn, int M, EPI epilogue)
{
    const uint32_t sbase = smem_u32(sm);
    const int t = threadIdx.x, lane = t & 31, wid = t >> 5;
    const int g = lane >> 2, tc = lane & 3;
    const int lr = lane & 7, grp = lane >> 3;
    const int warpM = wid & 1;
    const int warpN = wid >> 1;

    uint32_t aoff[4], boff[2];
#pragma unroll
    for (int mt = 0; mt < 4; mt++)
        aoff[mt] = (uint32_t)(warpM * 64 + mt * 16 + lr + ((grp & 1) << 3)) << 7;
#pragma unroll
    for (int np = 0; np < 2; np++)
        boff[np] = (uint32_t)(warpN * 32 + np * 16 + lr + ((grp >> 1) << 3)) << 7;
    const int acpar = grp >> 1;
    const int bcpar = grp & 1;

    float acc[4][4][4];
#pragma unroll
    for (int mt = 0; mt < 4; mt++)
#pragma unroll
        for (int nt = 0; nt < 4; nt++)
#pragma unroll
            for (int i = 0; i < 4; i++) acc[mt][nt][i] = 0.f;

    auto issue = [&](int kt, int stage) {
        const int k0 = kt * BKH;
        uint32_t dA = sbase + stage * STG;
        uint32_t dB = dA + ABYTES;
#pragma unroll
        for (int i = 0; i < 4; i++) {
            int idx = t + 256 * i;
            int row = idx >> 3;
            int c4  = idx & 7;
            uint32_t sw = ((uint32_t)row << 7) + ((uint32_t)(c4 ^ (row & 7)) << 4);
            int gm = bm + row;
            const __half* srcA = A + (size_t)(gm < M ? gm : 0) * D_ + k0 + c4 * 8;
            CP_ASYNC(dA + sw, srcA, (gm < M) ? 16 : 0);
            const __half* srcB = W + (size_t)(bn + row) * D_ + k0 + c4 * 8;
            CP_ASYNC(dB + sw, srcB, 16);
        }
        CP_COMMIT();
    };

    issue(0, 0);
    for (int kt = 0; kt < NKT; kt++) {
        const int buf = kt & 1;
        if (kt + 1 < NKT) { issue(kt + 1, buf ^ 1); CP_WAIT1(); }
        else              { CP_WAIT0(); }
        __syncthreads();

        const uint32_t sA = sbase + buf * STG;
        const uint32_t sB = sA + ABYTES;

#pragma unroll
        for (int ks = 0; ks < 4; ks++) {
            const uint32_t aco = (uint32_t)(((2 * ks + acpar) ^ lr) << 4);
            const uint32_t bco = (uint32_t)(((2 * ks + bcpar) ^ lr) << 4);

            uint32_t af[4][4];
#pragma unroll
            for (int mt = 0; mt < 4; mt++)
                ldsm_x4(af[mt], sA + aoff[mt] + aco);

            uint32_t bf[4][2];
#pragma unroll
            for (int np = 0; np < 2; np++) {
                uint32_t r[4];
                ldsm_x4(r, sB + boff[np] + bco);
                bf[2 * np][0]     = r[0];
                bf[2 * np][1]     = r[1];
                bf[2 * np + 1][0] = r[2];
                bf[2 * np + 1][1] = r[3];
            }
#pragma unroll
            for (int mt = 0; mt < 4; mt++)
#pragma unroll
                for (int nt = 0; nt < 4; nt++)
                    mma_f16(acc[mt][nt], af[mt], bf[nt]);
        }
        __syncthreads();
    }

#pragma unroll
    for (int nt = 0; nt < 4; nt++) {
        int c = bn + warpN * 32 + nt * 8 + tc * 2;
#pragma unroll
        for (int mt = 0; mt < 4; mt++) {
            int r0 = bm + warpM * 64 + mt * 16 + g;
            epilogue(r0,     c, acc[mt][nt][0], acc[mt][nt][1]);
            epilogue(r0 + 8, c, acc[mt][nt][2], acc[mt][nt][3]);
        }
    }
}

// ---------------------------------------------------------------------------
// Fused QKV GEMM + bias + rope (Q scaled). grid.x = 3*NBN.
// ---------------------------------------------------------------------------
__global__ __launch_bounds__(256, 2) void gemm_qkv_kernel(
    const __half* __restrict__ A, const __half* __restrict__ Wall,
    const float* __restrict__ bq, const float* __restrict__ bk,
    const float* __restrict__ bv, __half* __restrict__ Qh,
    __half* __restrict__ Kh, __half* __restrict__ Vh, int M)
{
    extern __shared__ __align__(128) char sm[];
    const int which = blockIdx.x / NBN;
    const int bn = (blockIdx.x % NBN) * BN;
    const int bm = blockIdx.y * BM;

    const __half* W = Wall + (size_t)which * D_ * D_;
    EpiQKV epi;
    epi.bias  = (which == 0) ? bq : (which == 1) ? bk : bv;
    epi.C     = (which == 0) ? Qh : (which == 1) ? Kh : Vh;
    epi.which = which;
    epi.M     = M;

    gemm_body(A, W, sm, bm, bn, M, epi);
}

// ---------------------------------------------------------------------------
// Plain GEMM + bias, fp32 output (final projection)
// ---------------------------------------------------------------------------
__global__ __launch_bounds__(256, 2) void gemm_out_kernel(
    const __half* __restrict__ A, const __half* __restrict__ W,
    const float* __restrict__ bias, float* __restrict__ C, int M)
{
    extern __shared__ __align__(128) char sm[];
    const int bn = blockIdx.x * BN;
    const int bm = blockIdx.y * BM;

    EpiOut epi; epi.bias = bias; epi.C = C; epi.M = M;
    gemm_body(A, W, sm, bm, bn, M, epi);
}

// ---------------------------------------------------------------------------
// Fused flash attention on mma.f16 — 3-buffer K/V rotation, ONE barrier/tile.
// Dynamic smem: Qs[QT*QSTR] + 3 x (Ks[KT*QSTR] + Vs[HD_*VSTR]).
// ---------------------------------------------------------------------------
#define QT   128
#define KT   32
#define QSTR 100
#define VSTR 36
constexpr int QS_HALFS  = QT * QSTR;                 // 12800
constexpr int KBUF_HALFS = KT * QSTR;                // 3200
constexpr int VBUF_HALFS = HD_ * VSTR;               // 3168
constexpr int BUF_HALFS  = KBUF_HALFS + VBUF_HALFS;  // 6368
constexpr int ATT_SMEM   = (QS_HALFS + 3 * BUF_HALFS) * 2;  // 63808 bytes

__global__ __launch_bounds__(256) void attn_mma_kernel(
    const __half* __restrict__ Q, const __half* __restrict__ K,
    const __half* __restrict__ V, __half* __restrict__ O)
{
    extern __shared__ __align__(16) __half smha[];
    __half* Qs = smha;

    const int qt = blockIdx.x, h = blockIdx.y, b = blockIdx.z;
    const int q0 = qt * QT;
    const int t = threadIdx.x, lane = t & 31, wid = t >> 5;
    const int g = lane >> 2, tc = lane & 3;

    // ---- stage Q tile ----
    for (int idx = t; idx < QT * 24; idx += 256) {
        int r = idx / 24, c = idx % 24;
        int s = q0 + r; if (s >= SEQ_) s = SEQ_ - 1;
        uint2 v = make_uint2(0u, 0u);
        if (c < 22)
            v = *(const uint2*)&Q[(((size_t)b * SEQ_ + s) * H_ + h) * HD_ + c * 4];
        *(uint2*)&Qs[r * QSTR + c * 4] = v;
    }
    __syncthreads();

    const int rw = wid * 16;
    uint32_t qf[6][4];
#pragma unroll
    for (int ks = 0; ks < 6; ks++) {
        const __half* p0 = &Qs[(rw + g) * QSTR + ks * 16 + 2 * tc];
        const __half* p1 = p0 + 8 * QSTR;
        qf[ks][0] = *(const uint32_t*)p0;
        qf[ks][1] = *(const uint32_t*)p1;
        qf[ks][2] = *(const uint32_t*)(p0 + 8);
        qf[ks][3] = *(const uint32_t*)(p1 + 8);
    }

    float oacc[11][4];
#pragma unroll
    for (int nt = 0; nt < 11; nt++)
#pragma unroll
        for (int i = 0; i < 4; i++) oacc[nt][i] = 0.f;
    float m0 = -1e30f, m1 = -1e30f, l0 = 0.f, l1 = 0.f;

    auto stage = [&](int k0, int bi) {
        __half* Ks = smha + QS_HALFS + bi * BUF_HALFS;
        __half* Vs = Ks + KBUF_HALFS;
        for (int idx = t; idx < KT * 24; idx += 256) {
            int r = idx / 24, c = idx % 24;
            int s = k0 + r;
            uint2 v = make_uint2(0u, 0u);
            if (s < SEQ_ && c < 22)
                v = *(const uint2*)&K[(((size_t)b * SEQ_ + s) * H_ + h) * HD_ + c * 4];
            *(uint2*)&Ks[r * QSTR + c * 4] = v;
        }
        for (int idx = t; idx < KT * 22; idx += 256) {
            int r = idx / 22, c = idx % 22;
            int s = k0 + r;
            uint2 v = make_uint2(0u, 0u);
            if (s < SEQ_)
                v = *(const uint2*)&V[(((size_t)b * SEQ_ + s) * H_ + h) * HD_ + c * 4];
            __half h4[4];
            *(uint2*)h4 = v;
#pragma unroll
            for (int j = 0; j < 4; j++)
                Vs[(c * 4 + j) * VSTR + r] = h4[j];
        }
    };

    constexpr int NT_ = (SEQ_ + KT - 1) / KT;   // 19
    stage(0, 0);

    for (int kt = 0; kt < NT_; kt++) {
        const int k0 = kt * KT;
        if (kt + 1 < NT_) stage(k0 + KT, (kt + 1) % 3);
        __syncthreads();   // staging of kt (and kt+1's in-flight writes are to a
                           // buffer last computed at kt-2, already drained)

        const __half* Ks = smha + QS_HALFS + (kt % 3) * BUF_HALFS;
        const __half* Vs = Ks + KBUF_HALFS;

        // ---- scores S(16x32) per warp ----
        float sc[4][4];
#pragma unroll
        for (int nt = 0; nt < 4; nt++)
#pragma unroll
            for (int i = 0; i < 4; i++) sc[nt][i] = 0.f;

#pragma unroll
        for (int ks = 0; ks < 6; ks++) {
#pragma unroll
            for (int nt = 0; nt < 4; nt++) {
                const __half* p = &Ks[(nt * 8 + g) * QSTR + ks * 16 + 2 * tc];
                uint32_t bf[2];
                bf[0] = *(const uint32_t*)p;
                bf[1] = *(const uint32_t*)(p + 8);
                mma_f16(sc[nt], qf[ks], bf);
            }
        }

        if (k0 + KT > SEQ_) {
#pragma unroll
            for (int nt = 0; nt < 4; nt++) {
                int kidx = k0 + nt * 8 + 2 * tc;
                if (kidx >= SEQ_)     { sc[nt][0] = -1e30f; sc[nt][2] = -1e30f; }
                if (kidx + 1 >= SEQ_) { sc[nt][1] = -1e30f; sc[nt][3] = -1e30f; }
            }
        }

        // ---- online softmax (warp-local) ----
        float mx0 = sc[0][0], mx1 = sc[0][2];
#pragma unroll
        for (int nt = 0; nt < 4; nt++) {
            mx0 = fmaxf(mx0, fmaxf(sc[nt][0], sc[nt][1]));
            mx1 = fmaxf(mx1, fmaxf(sc[nt][2], sc[nt][3]));
        }
        mx0 = fmaxf(mx0, __shfl_xor_sync(0xffffffffu, mx0, 1));
        mx0 = fmaxf(mx0, __shfl_xor_sync(0xffffffffu, mx0, 2));
        mx1 = fmaxf(mx1, __shfl_xor_sync(0xffffffffu, mx1, 1));
        mx1 = fmaxf(mx1, __shfl_xor_sync(0xffffffffu, mx1, 2));
        mx0 = fmaxf(mx0, m0); mx1 = fmaxf(mx1, m1);
        float corr0 = __expf(m0 - mx0), corr1 = __expf(m1 - mx1);
        m0 = mx0; m1 = mx1;

        float s0 = 0.f, s1 = 0.f;
#pragma unroll
        for (int nt = 0; nt < 4; nt++) {
            sc[nt][0] = __expf(sc[nt][0] - m0);
            sc[nt][1] = __expf(sc[nt][1] - m0);
            sc[nt][2] = __expf(sc[nt][2] - m1);
            sc[nt][3] = __expf(sc[nt][3] - m1);
            s0 += sc[nt][0] + sc[nt][1];
            s1 += sc[nt][2] + sc[nt][3];
        }
        s0 += __shfl_xor_sync(0xffffffffu, s0, 1);
        s0 += __shfl_xor_sync(0xffffffffu, s0, 2);
        s1 += __shfl_xor_sync(0xffffffffu, s1, 1);
        s1 += __shfl_xor_sync(0xffffffffu, s1, 2);
        l0 = l0 * corr0 + s0;
        l1 = l1 * corr1 + s1;

#pragma unroll
        for (int nt = 0; nt < 11; nt++) {
            oacc[nt][0] *= corr0; oacc[nt][1] *= corr0;
            oacc[nt][2] *= corr1; oacc[nt][3] *= corr1;
        }

        uint32_t pf[2][4];
#pragma unroll
        for (int kv = 0; kv < 2; kv++) {
            pf[kv][0] = packh2(sc[2 * kv][0],     sc[2 * kv][1]);
            pf[kv][1] = packh2(sc[2 * kv][2],     sc[2 * kv][3]);
            pf[kv][2] = packh2(sc[2 * kv + 1][0], sc[2 * kv + 1][1]);
            pf[kv][3] = packh2(sc[2 * kv + 1][2], sc[2 * kv + 1][3]);
        }

#pragma unroll
        for (int kv = 0; kv < 2; kv++) {
#pragma unroll
            for (int nt = 0; nt < 11; nt++) {
                const __half* p = &Vs[(nt * 8 + g) * VSTR + kv * 16 + 2 * tc];
                uint32_t bf[2];
                bf[0] = *(const uint32_t*)p;
                bf[1] = *(const uint32_t*)(p + 8);
                mma_f16(oacc[nt], pf[kv], bf);
            }
        }
    }

    float inv0 = 1.f / l0, inv1 = 1.f / l1;
    int s0 = q0 + rw + g, s1 = s0 + 8;
#pragma unroll
    for (int nt = 0; nt < 11; nt++) {
        int d = nt * 8 + 2 * tc;
        if (s0 < SEQ_)
            *(__half2*)&O[(((size_t)b * SEQ_ + s0) * H_ + h) * HD_ + d] =
                __floats2half2_rn(oacc[nt][0] * inv0, oacc[nt][1] * inv0);
        if (s1 < SEQ_)
            *(__half2*)&O[(((size_t)b * SEQ_ + s1) * H_ + h) * HD_ + d] =
                __floats2half2_rn(oacc[nt][2] * inv1, oacc[nt][3] * inv1);
    }
}

// ---------------------------------------------------------------------------
extern "C" void kernel_launch(void* const* d_in, const int* in_sizes, int n_in,
                              void* d_out, int out_size)
{
    const float* X  = (const float*)d_in[0];
    const float* wq = (const float*)d_in[1];
    const float* bq = (const float*)d_in[2];
    const float* wk = (const float*)d_in[3];
    const float* bk = (const float*)d_in[4];
    const float* wv = (const float*)d_in[5];
    const float* bv = (const float*)d_in[6];
    const float* wo = (const float*)d_in[7];
    const float* bo = (const float*)d_in[8];
    float* out = (float*)d_out;

    __half *Qh, *Kh, *Vh, *Xh, *Wh;
    cudaGetSymbolAddress((void**)&Qh, g_Qh);
    cudaGetSymbolAddress((void**)&Kh, g_Kh);
    cudaGetSymbolAddress((void**)&Vh, g_Vh);
    cudaGetSymbolAddress((void**)&Xh, g_Xh);
    cudaGetSymbolAddress((void**)&Wh, g_Wh);

    cudaFuncSetAttribute(gemm_qkv_kernel,
                         cudaFuncAttributeMaxDynamicSharedMemorySize, GSMEM);
    cudaFuncSetAttribute(gemm_out_kernel,
                         cudaFuncAttributeMaxDynamicSharedMemorySize, GSMEM);
    cudaFuncSetAttribute(attn_mma_kernel,
                         cudaFuncAttributeMaxDynamicSharedMemorySize, ATT_SMEM);

    const int WN4 = D_ * D_ / 4;
    const int XN4 = M_ * D_ / 4;
    f2h_kernel<<<(XN4 + 255) / 256, 256>>>(X, Xh, XN4);
    dim3 wgrid((WN4 + 255) / 256, 4);
    f2h4_kernel<<<wgrid, 256>>>(wq, wk, wv, wo, Wh, WN4);
    rope_init_kernel<<<(SEQ_ * 44 + 255) / 256, 256>>>();

    dim3 qgrid(3 * NBN, (M_ + BM - 1) / BM);   // (33, 145)
    gemm_qkv_kernel<<<qgrid, 256, GSMEM>>>(Xh, Wh, bq, bk, bv, Qh, Kh, Vh, M_);

    dim3 agrid((SEQ_ + QT - 1) / QT, H_, B_);  // (5, 16, 32)
    attn_mma_kernel<<<agrid, 256, ATT_SMEM>>>(Qh, Kh, Vh, Xh);

    dim3 ogrid(NBN, (M_ + BM - 1) / BM);       // (11, 145)
    gemm_out_kernel<<<ogrid, 256, GSMEM>>>(Xh, Wh + 3 * (size_t)D_ * D_, bo, out, M_);
}

// round 15
// speedup vs baseline: 1.2636x; 1.2172x over previous
#include <cuda_runtime.h>
#include <cuda_fp16.h>
#include <math.h>
#include <stdint.h>

// Problem constants
#define B_   32
#define SEQ_ 577
#define H_   16
#define HD_  88
#define D_   1408
#define IDX_ 24
#define M_   (B_ * SEQ_)   // 18464

// Scratch (device globals)
__device__ __half g_Qh[(size_t)M_ * D_];
__device__ __half g_Kh[(size_t)M_ * D_];
__device__ __half g_Vh[(size_t)M_ * D_];
__device__ __half g_Xh[(size_t)M_ * D_];
__device__ __half g_Wh[4][(size_t)D_ * D_];
__device__ float  g_cos[SEQ_ * 44];
__device__ float  g_sin[SEQ_ * 44];

// ---------------------------------------------------------------------------
// helpers
// ---------------------------------------------------------------------------
__device__ __forceinline__ uint32_t smem_u32(const void* p) {
    uint32_t a;
    asm("{ .reg .u64 t; cvta.to.shared.u64 t, %1; cvt.u32.u64 %0, t; }" : "=r"(a) : "l"(p));
    return a;
}
__device__ __forceinline__ void mma_f16(float* d, const uint32_t* a, const uint32_t* b) {
    asm volatile(
        "mma.sync.aligned.m16n8k16.row.col.f32.f16.f16.f32 "
        "{%0,%1,%2,%3},{%4,%5,%6,%7},{%8,%9},{%0,%1,%2,%3};"
        : "+f"(d[0]), "+f"(d[1]), "+f"(d[2]), "+f"(d[3])
        : "r"(a[0]), "r"(a[1]), "r"(a[2]), "r"(a[3]), "r"(b[0]), "r"(b[1]));
}
__device__ __forceinline__ void ldsm_x4(uint32_t* r, uint32_t addr) {
    asm volatile("ldmatrix.sync.aligned.m8n8.x4.shared.b16 {%0,%1,%2,%3}, [%4];"
                 : "=r"(r[0]), "=r"(r[1]), "=r"(r[2]), "=r"(r[3]) : "r"(addr));
}
__device__ __forceinline__ void ldsm_x4_t(uint32_t* r, uint32_t addr) {
    asm volatile("ldmatrix.sync.aligned.m8n8.x4.trans.shared.b16 {%0,%1,%2,%3}, [%4];"
                 : "=r"(r[0]), "=r"(r[1]), "=r"(r[2]), "=r"(r[3]) : "r"(addr));
}
__device__ __forceinline__ void ldsm_x2_t(uint32_t* r, uint32_t addr) {
    asm volatile("ldmatrix.sync.aligned.m8n8.x2.trans.shared.b16 {%0,%1}, [%2];"
                 : "=r"(r[0]), "=r"(r[1]) : "r"(addr));
}
__device__ __forceinline__ uint32_t packh2(float lo, float hi) {
    __half2 h = __floats2half2_rn(lo, hi);
    return *(uint32_t*)&h;
}

#define CP_ASYNC(dst, src, sz) \
    asm volatile("cp.async.cg.shared.global [%0], [%1], 16, %2;" \
                 :: "r"(dst), "l"(src), "r"(sz) : "memory")
#define CP_COMMIT() asm volatile("cp.async.commit_group;" ::: "memory")
#define CP_WAIT1()  asm volatile("cp.async.wait_group 1;" ::: "memory")
#define CP_WAIT0()  asm volatile("cp.async.wait_group 0;" ::: "memory")

// ---------------------------------------------------------------------------
// fp32 -> fp16 conversions
// ---------------------------------------------------------------------------
__global__ void f2h_kernel(const float* __restrict__ in,
                           __half* __restrict__ out, int n4)
{
    int i = blockIdx.x * blockDim.x + threadIdx.x;
    if (i >= n4) return;
    float4 v = ((const float4*)in)[i];
    ((__half2*)out)[2 * i]     = __floats2half2_rn(v.x, v.y);
    ((__half2*)out)[2 * i + 1] = __floats2half2_rn(v.z, v.w);
}

__global__ void f2h4_kernel(const float* __restrict__ w0, const float* __restrict__ w1,
                            const float* __restrict__ w2, const float* __restrict__ w3,
                            __half* __restrict__ out, int n4)
{
    int i = blockIdx.x * blockDim.x + threadIdx.x;
    if (i >= n4) return;
    const float* in = (blockIdx.y == 0) ? w0 : (blockIdx.y == 1) ? w1
                     : (blockIdx.y == 2) ? w2 : w3;
    __half* o = out + (size_t)blockIdx.y * D_ * D_;
    float4 v = ((const float4*)in)[i];
    ((__half2*)o)[2 * i]     = __floats2half2_rn(v.x, v.y);
    ((__half2*)o)[2 * i + 1] = __floats2half2_rn(v.z, v.w);
}

// ---------------------------------------------------------------------------
// Rope tables
// ---------------------------------------------------------------------------
__global__ void rope_init_kernel()
{
    int idx = blockIdx.x * blockDim.x + threadIdx.x;
    if (idx >= SEQ_ * 44) return;
    int s = idx / 44, j = idx % 44;
    double f = 0.0;
    if (s != SEQ_ - 1) {
        int fx = s % IDX_, fy = s / IDX_;
        int i = (j < 22) ? j : j - 22;
        double rf = exp((-2.0 * (double)i / 44.0) * log(10000.0));
        double coord = (j < 22) ? (double)(fx + 1) : (double)(fy + 1);
        f = coord * rf;
    }
    g_cos[idx] = (float)cos(f);
    g_sin[idx] = (float)sin(f);
}

// ---------------------------------------------------------------------------
// GEMM tile config — R11 2-stage pipeline (proven fastest)
// ---------------------------------------------------------------------------
constexpr int BM = 128, BN = 128, BKH = 64;
constexpr int NKT = D_ / BKH;             // 22
constexpr int ABYTES = BM * 128;          // 16384
constexpr int STG    = 2 * ABYTES;        // 32768
constexpr int GSMEM  = 2 * STG;           // 65536
constexpr int NBN    = D_ / BN;           // 11

// ---------------------------------------------------------------------------
// Epilogue functors
// ---------------------------------------------------------------------------
struct EpiQKV {
    const float* bias;
    __half* C;
    int which;   // 0=Q 1=K 2=V
    int M;
    __device__ __forceinline__ void operator()(int r, int c, float v0, float v1) const {
        if (r >= M) return;
        v0 += bias[c];
        v1 += bias[c + 1];
        if (which < 2) {
            int s = r % SEQ_;
            int j = (c % HD_) >> 1;
            float cs = g_cos[s * 44 + j];
            float sn = g_sin[s * 44 + j];
            float a = v0, b = v1;
            v0 = a * cs - b * sn;
            v1 = a * sn + b * cs;
            if (which == 0) {
                const float qscale = 0.10660035817780521f;
                v0 *= qscale; v1 *= qscale;
            }
        }
        *(__half2*)&C[(size_t)r * D_ + c] = __floats2half2_rn(v0, v1);
    }
};

struct EpiOut {
    const float* bias;
    float* C;
    int M;
    __device__ __forceinline__ void operator()(int r, int c, float v0, float v1) const {
        if (r >= M) return;
        *(float2*)&C[(size_t)r * D_ + c] =
            make_float2(v0 + bias[c], v1 + bias[c + 1]);
    }
};

// Shared GEMM mainloop (one 128x128 tile), ldmatrix feed, 2-stage pipeline.
template <typename EPI>
__device__ __forceinline__ void gemm_body(
    const __half* __restrict__ A, const __half* __restrict__ W,
    char* sm, int bm, int bn, int M, EPI epilogue)
{
    const uint32_t sbase = smem_u32(sm);
    const int t = threadIdx.x, lane = t & 31, wid = t >> 5;
    const int g = lane >> 2, tc = lane & 3;
    const int lr = lane & 7, grp = lane >> 3;
    const int warpM = wid & 1;
    const int warpN = wid >> 1;

    uint32_t aoff[4], boff[2];
#pragma unroll
    for (int mt = 0; mt < 4; mt++)
        aoff[mt] = (uint32_t)(warpM * 64 + mt * 16 + lr + ((grp & 1) << 3)) << 7;
#pragma unroll
    for (int np = 0; np < 2; np++)
        boff[np] = (uint32_t)(warpN * 32 + np * 16 + lr + ((grp >> 1) << 3)) << 7;
    const int acpar = grp >> 1;
    const int bcpar = grp & 1;

    float acc[4][4][4];
#pragma unroll
    for (int mt = 0; mt < 4; mt++)
#pragma unroll
        for (int nt = 0; nt < 4; nt++)
#pragma unroll
            for (int i = 0; i < 4; i++) acc[mt][nt][i] = 0.f;

    auto issue = [&](int kt, int stage) {
        const int k0 = kt * BKH;
        uint32_t dA = sbase + stage * STG;
        uint32_t dB = dA + ABYTES;
#pragma unroll
        for (int i = 0; i < 4; i++) {
            int idx = t + 256 * i;
            int row = idx >> 3;
            int c4  = idx & 7;
            uint32_t sw = ((uint32_t)row << 7) + ((uint32_t)(c4 ^ (row & 7)) << 4);
            int gm = bm + row;
            const __half* srcA = A + (size_t)(gm < M ? gm : 0) * D_ + k0 + c4 * 8;
            CP_ASYNC(dA + sw, srcA, (gm < M) ? 16 : 0);
            const __half* srcB = W + (size_t)(bn + row) * D_ + k0 + c4 * 8;
            CP_ASYNC(dB + sw, srcB, 16);
        }
        CP_COMMIT();
    };

    issue(0, 0);
    for (int kt = 0; kt < NKT; kt++) {
        const int buf = kt & 1;
        if (kt + 1 < NKT) { issue(kt + 1, buf ^ 1); CP_WAIT1(); }
        else              { CP_WAIT0(); }
        __syncthreads();

        const uint32_t sA = sbase + buf * STG;
        const uint32_t sB = sA + ABYTES;

#pragma unroll
        for (int ks = 0; ks < 4; ks++) {
            const uint32_t aco = (uint32_t)(((2 * ks + acpar) ^ lr) << 4);
            const uint32_t bco = (uint32_t)(((2 * ks + bcpar) ^ lr) << 4);

            uint32_t af[4][4];
#pragma unroll
            for (int mt = 0; mt < 4; mt++)
                ldsm_x4(af[mt], sA + aoff[mt] + aco);

            uint32_t bf[4][2];
#pragma unroll
            for (int np = 0; np < 2; np++) {
                uint32_t r[4];
                ldsm_x4(r, sB + boff[np] + bco);
                bf[2 * np][0]     = r[0];
                bf[2 * np][1]     = r[1];
                bf[2 * np + 1][0] = r[2];
                bf[2 * np + 1][1] = r[3];
            }
#pragma unroll
            for (int mt = 0; mt < 4; mt++)
#pragma unroll
                for (int nt = 0; nt < 4; nt++)
                    mma_f16(acc[mt][nt], af[mt], bf[nt]);
        }
        __syncthreads();
    }

#pragma unroll
    for (int nt = 0; nt < 4; nt++) {
        int c = bn + warpN * 32 + nt * 8 + tc * 2;
#pragma unroll
        for (int mt = 0; mt < 4; mt++) {
            int r0 = bm + warpM * 64 + mt * 16 + g;
            epilogue(r0,     c, acc[mt][nt][0], acc[mt][nt][1]);
            epilogue(r0 + 8, c, acc[mt][nt][2], acc[mt][nt][3]);
        }
    }
}

// ---------------------------------------------------------------------------
// Fused QKV GEMM + bias + rope (Q scaled). grid.x = 3*NBN.
// ---------------------------------------------------------------------------
__global__ __launch_bounds__(256, 2) void gemm_qkv_kernel(
    const __half* __restrict__ A, const __half* __restrict__ Wall,
    const float* __restrict__ bq, const float* __restrict__ bk,
    const float* __restrict__ bv, __half* __restrict__ Qh,
    __half* __restrict__ Kh, __half* __restrict__ Vh, int M)
{
    extern __shared__ __align__(128) char sm[];
    const int which = blockIdx.x / NBN;
    const int bn = (blockIdx.x % NBN) * BN;
    const int bm = blockIdx.y * BM;

    const __half* W = Wall + (size_t)which * D_ * D_;
    EpiQKV epi;
    epi.bias  = (which == 0) ? bq : (which == 1) ? bk : bv;
    epi.C     = (which == 0) ? Qh : (which == 1) ? Kh : Vh;
    epi.which = which;
    epi.M     = M;

    gemm_body(A, W, sm, bm, bn, M, epi);
}

// ---------------------------------------------------------------------------
// Plain GEMM + bias, fp32 output (final projection)
// ---------------------------------------------------------------------------
__global__ __launch_bounds__(256, 2) void gemm_out_kernel(
    const __half* __restrict__ A, const __half* __restrict__ W,
    const float* __restrict__ bias, float* __restrict__ C, int M)
{
    extern __shared__ __align__(128) char sm[];
    const int bn = blockIdx.x * BN;
    const int bm = blockIdx.y * BM;

    EpiOut epi; epi.bias = bias; epi.C = C; epi.M = M;
    gemm_body(A, W, sm, bm, bn, M, epi);
}

// ---------------------------------------------------------------------------
// Fused flash attention: ldmatrix fragment feeds (K non-trans, V trans),
// row-major V staging, 3-buffer K/V rotation with one barrier per tile.
// ---------------------------------------------------------------------------
#define QT   128
#define KT   32
#define QSTR 104                                  // halfs/row: 208B, 16B-aligned
constexpr int QS_HALFS   = QT * QSTR;             // 13312
constexpr int KBUF_HALFS = KT * QSTR;             // 3328
constexpr int VBUF_HALFS = KT * QSTR;             // 3328 (row-major V)
constexpr int BUF_HALFS  = KBUF_HALFS + VBUF_HALFS;
constexpr int ATT_SMEM   = (QS_HALFS + 3 * BUF_HALFS) * 2;   // 66560 bytes

__global__ __launch_bounds__(256) void attn_mma_kernel(
    const __half* __restrict__ Q, const __half* __restrict__ K,
    const __half* __restrict__ V, __half* __restrict__ O)
{
    extern __shared__ __align__(16) __half smha[];
    __half* Qs = smha;
    const uint32_t smbase = smem_u32(smha);

    const int qt = blockIdx.x, h = blockIdx.y, b = blockIdx.z;
    const int q0 = qt * QT;
    const int t = threadIdx.x, lane = t & 31, wid = t >> 5;
    const int g = lane >> 2, tc = lane & 3;
    const int lr = lane & 7, grp = lane >> 3;

    // ---- stage Q tile (zero-padded cols 88..95) ----
    for (int idx = t; idx < QT * 24; idx += 256) {
        int r = idx / 24, c = idx % 24;
        int s = q0 + r; if (s >= SEQ_) s = SEQ_ - 1;
        uint2 v = make_uint2(0u, 0u);
        if (c < 22)
            v = *(const uint2*)&Q[(((size_t)b * SEQ_ + s) * H_ + h) * HD_ + c * 4];
        *(uint2*)&Qs[r * QSTR + c * 4] = v;
    }
    __syncthreads();

    const int rw = wid * 16;
    uint32_t qf[6][4];
#pragma unroll
    for (int ks = 0; ks < 6; ks++) {
        const __half* p0 = &Qs[(rw + g) * QSTR + ks * 16 + 2 * tc];
        const __half* p1 = p0 + 8 * QSTR;
        qf[ks][0] = *(const uint32_t*)p0;
        qf[ks][1] = *(const uint32_t*)p1;
        qf[ks][2] = *(const uint32_t*)(p0 + 8);
        qf[ks][3] = *(const uint32_t*)(p1 + 8);
    }

    // ldmatrix per-lane base offsets (bytes, relative to K/V buffer base)
    // K (non-trans): np in {0,1}: rows np*16 + lr + (grp>>1)*8; chunk parity grp&1
    uint32_t koff[2];
#pragma unroll
    for (int np = 0; np < 2; np++)
        koff[np] = (uint32_t)(np * 16 + lr + ((grp >> 1) << 3)) * (QSTR * 2);
    const uint32_t kcpar = (uint32_t)(grp & 1);
    // V (trans): rows kv*16 + (grp&1)*8 + lr; col pair parity grp>>1
    const uint32_t vrow = (uint32_t)(((grp & 1) << 3) + lr) * (QSTR * 2);
    const uint32_t vcpar = (uint32_t)(grp >> 1);

    float oacc[11][4];
#pragma unroll
    for (int nt = 0; nt < 11; nt++)
#pragma unroll
        for (int i = 0; i < 4; i++) oacc[nt][i] = 0.f;
    float m0 = -1e30f, m1 = -1e30f, l0 = 0.f, l1 = 0.f;

    auto stage = [&](int k0, int bi) {
        __half* Ks = smha + QS_HALFS + bi * BUF_HALFS;
        __half* Vs = Ks + KBUF_HALFS;
        for (int idx = t; idx < KT * 24; idx += 256) {
            int r = idx / 24, c = idx % 24;
            int s = k0 + r;
            uint2 kv = make_uint2(0u, 0u), vv = make_uint2(0u, 0u);
            if (s < SEQ_ && c < 22) {
                size_t gg = (((size_t)b * SEQ_ + s) * H_ + h) * HD_ + c * 4;
                kv = *(const uint2*)&K[gg];
                vv = *(const uint2*)&V[gg];
            }
            *(uint2*)&Ks[r * QSTR + c * 4] = kv;
            *(uint2*)&Vs[r * QSTR + c * 4] = vv;
        }
    };

    constexpr int NT_ = (SEQ_ + KT - 1) / KT;   // 19
    stage(0, 0);

    for (int kt = 0; kt < NT_; kt++) {
        const int k0 = kt * KT;
        if (kt + 1 < NT_) stage(k0 + KT, (kt + 1) % 3);
        __syncthreads();

        const uint32_t sK = smbase + (QS_HALFS + (kt % 3) * BUF_HALFS) * 2;
        const uint32_t sV = sK + KBUF_HALFS * 2;

        // ---- scores S(16x32) per warp: ldmatrix K fragments ----
        float sc[4][4];
#pragma unroll
        for (int nt = 0; nt < 4; nt++)
#pragma unroll
            for (int i = 0; i < 4; i++) sc[nt][i] = 0.f;

#pragma unroll
        for (int ks = 0; ks < 6; ks++) {
            uint32_t bf[4][2];
#pragma unroll
            for (int np = 0; np < 2; np++) {
                uint32_t r[4];
                ldsm_x4(r, sK + koff[np] + (2 * ks + kcpar) * 16);
                bf[2 * np][0]     = r[0];
                bf[2 * np][1]     = r[1];
                bf[2 * np + 1][0] = r[2];
                bf[2 * np + 1][1] = r[3];
            }
#pragma unroll
            for (int nt = 0; nt < 4; nt++)
                mma_f16(sc[nt], qf[ks], bf[nt]);
        }

        if (k0 + KT > SEQ_) {
#pragma unroll
            for (int nt = 0; nt < 4; nt++) {
                int kidx = k0 + nt * 8 + 2 * tc;
                if (kidx >= SEQ_)     { sc[nt][0] = -1e30f; sc[nt][2] = -1e30f; }
                if (kidx + 1 >= SEQ_) { sc[nt][1] = -1e30f; sc[nt][3] = -1e30f; }
            }
        }

        // ---- online softmax (warp-local) ----
        float mx0 = sc[0][0], mx1 = sc[0][2];
#pragma unroll
        for (int nt = 0; nt < 4; nt++) {
            mx0 = fmaxf(mx0, fmaxf(sc[nt][0], sc[nt][1]));
            mx1 = fmaxf(mx1, fmaxf(sc[nt][2], sc[nt][3]));
        }
        mx0 = fmaxf(mx0, __shfl_xor_sync(0xffffffffu, mx0, 1));
        mx0 = fmaxf(mx0, __shfl_xor_sync(0xffffffffu, mx0, 2));
        mx1 = fmaxf(mx1, __shfl_xor_sync(0xffffffffu, mx1, 1));
        mx1 = fmaxf(mx1, __shfl_xor_sync(0xffffffffu, mx1, 2));
        mx0 = fmaxf(mx0, m0); mx1 = fmaxf(mx1, m1);
        float corr0 = __expf(m0 - mx0), corr1 = __expf(m1 - mx1);
        m0 = mx0; m1 = mx1;

        float s0 = 0.f, s1 = 0.f;
#pragma unroll
        for (int nt = 0; nt < 4; nt++) {
            sc[nt][0] = __expf(sc[nt][0] - m0);
            sc[nt][1] = __expf(sc[nt][1] - m0);
            sc[nt][2] = __expf(sc[nt][2] - m1);
            sc[nt][3] = __expf(sc[nt][3] - m1);
            s0 += sc[nt][0] + sc[nt][1];
            s1 += sc[nt][2] + sc[nt][3];
        }
        s0 += __shfl_xor_sync(0xffffffffu, s0, 1);
        s0 += __shfl_xor_sync(0xffffffffu, s0, 2);
        s1 += __shfl_xor_sync(0xffffffffu, s1, 1);
        s1 += __shfl_xor_sync(0xffffffffu, s1, 2);
        l0 = l0 * corr0 + s0;
        l1 = l1 * corr1 + s1;

#pragma unroll
        for (int nt = 0; nt < 11; nt++) {
            oacc[nt][0] *= corr0; oacc[nt][1] *= corr0;
            oacc[nt][2] *= corr1; oacc[nt][3] *= corr1;
        }

        uint32_t pf[2][4];
#pragma unroll
        for (int kv = 0; kv < 2; kv++) {
            pf[kv][0] = packh2(sc[2 * kv][0],     sc[2 * kv][1]);
            pf[kv][1] = packh2(sc[2 * kv][2],     sc[2 * kv][3]);
            pf[kv][2] = packh2(sc[2 * kv + 1][0], sc[2 * kv + 1][1]);
            pf[kv][3] = packh2(sc[2 * kv + 1][2], sc[2 * kv + 1][3]);
        }

        // ---- PV: trans-ldmatrix V fragments from row-major Vs ----
#pragma unroll
        for (int kv = 0; kv < 2; kv++) {
            uint32_t vb = sV + (uint32_t)(kv * 16) * (QSTR * 2) + vrow;
            uint32_t bf[11][2];
#pragma unroll
            for (int npv = 0; npv < 5; npv++) {
                uint32_t r[4];
                ldsm_x4_t(r, vb + (npv * 2 + vcpar) * 16);
                bf[2 * npv][0]     = r[0];
                bf[2 * npv][1]     = r[1];
                bf[2 * npv + 1][0] = r[2];
                bf[2 * npv + 1][1] = r[3];
            }
            {
                // nt = 10: x2 (lanes 0-15 addresses: rows kv*16 + (lane>>3)*8 + lr)
                uint32_t r[2];
                uint32_t addr = sV + (uint32_t)(kv * 16 + ((lane >> 3) & 1) * 8 + lr) * (QSTR * 2)
                              + 10 * 16;
                ldsm_x2_t(r, addr);
                bf[10][0] = r[0];
                bf[10][1] = r[1];
            }
#pragma unroll
            for (int nt = 0; nt < 11; nt++)
                mma_f16(oacc[nt], pf[kv], bf[nt]);
        }
    }

    float inv0 = 1.f / l0, inv1 = 1.f / l1;
    int s0 = q0 + rw + g, s1 = s0 + 8;
#pragma unroll
    for (int nt = 0; nt < 11; nt++) {
        int d = nt * 8 + 2 * tc;
        if (s0 < SEQ_)
            *(__half2*)&O[(((size_t)b * SEQ_ + s0) * H_ + h) * HD_ + d] =
                __floats2half2_rn(oacc[nt][0] * inv0, oacc[nt][1] * inv0);
        if (s1 < SEQ_)
            *(__half2*)&O[(((size_t)b * SEQ_ + s1) * H_ + h) * HD_ + d] =
                __floats2half2_rn(oacc[nt][2] * inv1, oacc[nt][3] * inv1);
    }
}

// ---------------------------------------------------------------------------
extern "C" void kernel_launch(void* const* d_in, const int* in_sizes, int n_in,
                              void* d_out, int out_size)
{
    const float* X  = (const float*)d_in[0];
    const float* wq = (const float*)d_in[1];
    const float* bq = (const float*)d_in[2];
    const float* wk = (const float*)d_in[3];
    const float* bk = (const float*)d_in[4];
    const float* wv = (const float*)d_in[5];
    const float* bv = (const float*)d_in[6];
    const float* wo = (const float*)d_in[7];
    const float* bo = (const float*)d_in[8];
    float* out = (float*)d_out;

    __half *Qh, *Kh, *Vh, *Xh, *Wh;
    cudaGetSymbolAddress((void**)&Qh, g_Qh);
    cudaGetSymbolAddress((void**)&Kh, g_Kh);
    cudaGetSymbolAddress((void**)&Vh, g_Vh);
    cudaGetSymbolAddress((void**)&Xh, g_Xh);
    cudaGetSymbolAddress((void**)&Wh, g_Wh);

    cudaFuncSetAttribute(gemm_qkv_kernel,
                         cudaFuncAttributeMaxDynamicSharedMemorySize, GSMEM);
    cudaFuncSetAttribute(gemm_out_kernel,
                         cudaFuncAttributeMaxDynamicSharedMemorySize, GSMEM);
    cudaFuncSetAttribute(attn_mma_kernel,
                         cudaFuncAttributeMaxDynamicSharedMemorySize, ATT_SMEM);

    const int WN4 = D_ * D_ / 4;
    const int XN4 = M_ * D_ / 4;
    f2h_kernel<<<(XN4 + 255) / 256, 256>>>(X, Xh, XN4);
    dim3 wgrid((WN4 + 255) / 256, 4);
    f2h4_kernel<<<wgrid, 256>>>(wq, wk, wv, wo, Wh, WN4);
    rope_init_kernel<<<(SEQ_ * 44 + 255) / 256, 256>>>();

    dim3 qgrid(3 * NBN, (M_ + BM - 1) / BM);   // (33, 145)
    gemm_qkv_kernel<<<qgrid, 256, GSMEM>>>(Xh, Wh, bq, bk, bv, Qh, Kh, Vh, M_);

    dim3 agrid((SEQ_ + QT - 1) / QT, H_, B_);  // (5, 16, 32)
    attn_mma_kernel<<<agrid, 256, ATT_SMEM>>>(Qh, Kh, Vh, Xh);

    dim3 ogrid(NBN, (M_ + BM - 1) / BM);       // (11, 145)
    gemm_out_kernel<<<ogrid, 256, GSMEM>>>(Xh, Wh + 3 * (size_t)D_ * D_, bo, out, M_);
}

// round 16
// speedup vs baseline: 1.3683x; 1.0828x over previous
#include <cuda_runtime.h>
#include <cuda_fp16.h>
#include <math.h>
#include <stdint.h>

// Problem constants
#define B_   32
#define SEQ_ 577
#define H_   16
#define HD_  88
#define D_   1408
#define IDX_ 24
#define M_   (B_ * SEQ_)   // 18464

// Scratch (device globals)
__device__ __half g_Qh[(size_t)M_ * D_];
__device__ __half g_Kh[(size_t)M_ * D_];
__device__ __half g_Vh[(size_t)M_ * D_];
__device__ __half g_Xh[(size_t)M_ * D_];
__device__ __half g_Wh[4][(size_t)D_ * D_];
__device__ float  g_cos[SEQ_ * 44];
__device__ float  g_sin[SEQ_ * 44];

// ---------------------------------------------------------------------------
// helpers
// ---------------------------------------------------------------------------
__device__ __forceinline__ uint32_t smem_u32(const void* p) {
    uint32_t a;
    asm("{ .reg .u64 t; cvta.to.shared.u64 t, %1; cvt.u32.u64 %0, t; }" : "=r"(a) : "l"(p));
    return a;
}
__device__ __forceinline__ void mma_f16(float* d, const uint32_t* a, const uint32_t* b) {
    asm volatile(
        "mma.sync.aligned.m16n8k16.row.col.f32.f16.f16.f32 "
        "{%0,%1,%2,%3},{%4,%5,%6,%7},{%8,%9},{%0,%1,%2,%3};"
        : "+f"(d[0]), "+f"(d[1]), "+f"(d[2]), "+f"(d[3])
        : "r"(a[0]), "r"(a[1]), "r"(a[2]), "r"(a[3]), "r"(b[0]), "r"(b[1]));
}
__device__ __forceinline__ void ldsm_x4(uint32_t* r, uint32_t addr) {
    asm volatile("ldmatrix.sync.aligned.m8n8.x4.shared.b16 {%0,%1,%2,%3}, [%4];"
                 : "=r"(r[0]), "=r"(r[1]), "=r"(r[2]), "=r"(r[3]) : "r"(addr));
}
__device__ __forceinline__ void ldsm_x4_t(uint32_t* r, uint32_t addr) {
    asm volatile("ldmatrix.sync.aligned.m8n8.x4.trans.shared.b16 {%0,%1,%2,%3}, [%4];"
                 : "=r"(r[0]), "=r"(r[1]), "=r"(r[2]), "=r"(r[3]) : "r"(addr));
}
__device__ __forceinline__ void ldsm_x2_t(uint32_t* r, uint32_t addr) {
    asm volatile("ldmatrix.sync.aligned.m8n8.x2.trans.shared.b16 {%0,%1}, [%2];"
                 : "=r"(r[0]), "=r"(r[1]) : "r"(addr));
}
__device__ __forceinline__ uint32_t packh2(float lo, float hi) {
    __half2 h = __floats2half2_rn(lo, hi);
    return *(uint32_t*)&h;
}

#define CP_ASYNC(dst, src, sz) \
    asm volatile("cp.async.cg.shared.global [%0], [%1], 16, %2;" \
                 :: "r"(dst), "l"(src), "r"(sz) : "memory")
#define CP_COMMIT() asm volatile("cp.async.commit_group;" ::: "memory")
#define CP_WAIT1()  asm volatile("cp.async.wait_group 1;" ::: "memory")
#define CP_WAIT0()  asm volatile("cp.async.wait_group 0;" ::: "memory")

// ---------------------------------------------------------------------------
// fp32 -> fp16 conversions
// ---------------------------------------------------------------------------
__global__ void f2h_kernel(const float* __restrict__ in,
                           __half* __restrict__ out, int n4)
{
    int i = blockIdx.x * blockDim.x + threadIdx.x;
    if (i >= n4) return;
    float4 v = ((const float4*)in)[i];
    ((__half2*)out)[2 * i]     = __floats2half2_rn(v.x, v.y);
    ((__half2*)out)[2 * i + 1] = __floats2half2_rn(v.z, v.w);
}

__global__ void f2h4_kernel(const float* __restrict__ w0, const float* __restrict__ w1,
                            const float* __restrict__ w2, const float* __restrict__ w3,
                            __half* __restrict__ out, int n4)
{
    int i = blockIdx.x * blockDim.x + threadIdx.x;
    if (i >= n4) return;
    const float* in = (blockIdx.y == 0) ? w0 : (blockIdx.y == 1) ? w1
                     : (blockIdx.y == 2) ? w2 : w3;
    __half* o = out + (size_t)blockIdx.y * D_ * D_;
    float4 v = ((const float4*)in)[i];
    ((__half2*)o)[2 * i]     = __floats2half2_rn(v.x, v.y);
    ((__half2*)o)[2 * i + 1] = __floats2half2_rn(v.z, v.w);
}

// ---------------------------------------------------------------------------
// Rope tables
// ---------------------------------------------------------------------------
__global__ void rope_init_kernel()
{
    int idx = blockIdx.x * blockDim.x + threadIdx.x;
    if (idx >= SEQ_ * 44) return;
    int s = idx / 44, j = idx % 44;
    double f = 0.0;
    if (s != SEQ_ - 1) {
        int fx = s % IDX_, fy = s / IDX_;
        int i = (j < 22) ? j : j - 22;
        double rf = exp((-2.0 * (double)i / 44.0) * log(10000.0));
        double coord = (j < 22) ? (double)(fx + 1) : (double)(fy + 1);
        f = coord * rf;
    }
    g_cos[idx] = (float)cos(f);
    g_sin[idx] = (float)sin(f);
}

// ---------------------------------------------------------------------------
// GEMM tile config — R11 2-stage pipeline (proven fastest)
// ---------------------------------------------------------------------------
constexpr int BM = 128, BN = 128, BKH = 64;
constexpr int NKT = D_ / BKH;             // 22
constexpr int ABYTES = BM * 128;          // 16384
constexpr int STG    = 2 * ABYTES;        // 32768
constexpr int GSMEM  = 2 * STG;           // 65536
constexpr int NBN    = D_ / BN;           // 11

// ---------------------------------------------------------------------------
// Epilogue functors
// ---------------------------------------------------------------------------
struct EpiQKV {
    const float* bias;
    __half* C;
    int which;   // 0=Q 1=K 2=V
    int M;
    __device__ __forceinline__ void operator()(int r, int c, float v0, float v1) const {
        if (r >= M) return;
        v0 += bias[c];
        v1 += bias[c + 1];
        if (which < 2) {
            int s = r % SEQ_;
            int j = (c % HD_) >> 1;
            float cs = g_cos[s * 44 + j];
            float sn = g_sin[s * 44 + j];
            float a = v0, b = v1;
            v0 = a * cs - b * sn;
            v1 = a * sn + b * cs;
            if (which == 0) {
                const float qscale = 0.10660035817780521f;
                v0 *= qscale; v1 *= qscale;
            }
        }
        *(__half2*)&C[(size_t)r * D_ + c] = __floats2half2_rn(v0, v1);
    }
};

struct EpiOut {
    const float* bias;
    float* C;
    int M;
    __device__ __forceinline__ void operator()(int r, int c, float v0, float v1) const {
        if (r >= M) return;
        *(float2*)&C[(size_t)r * D_ + c] =
            make_float2(v0 + bias[c], v1 + bias[c + 1]);
    }
};

// Shared GEMM mainloop (one 128x128 tile), ldmatrix feed, 2-stage pipeline.
template <typename EPI>
__device__ __forceinline__ void gemm_body(
    const __half* __restrict__ A, const __half* __restrict__ W,
    char* sm, int bm, int bn, int M, EPI epilogue)
{
    const uint32_t sbase = smem_u32(sm);
    const int t = threadIdx.x, lane = t & 31, wid = t >> 5;
    const int g = lane >> 2, tc = lane & 3;
    const int lr = lane & 7, grp = lane >> 3;
    const int warpM = wid & 1;
    const int warpN = wid >> 1;

    uint32_t aoff[4], boff[2];
#pragma unroll
    for (int mt = 0; mt < 4; mt++)
        aoff[mt] = (uint32_t)(warpM * 64 + mt * 16 + lr + ((grp & 1) << 3)) << 7;
#pragma unroll
    for (int np = 0; np < 2; np++)
        boff[np] = (uint32_t)(warpN * 32 + np * 16 + lr + ((grp >> 1) << 3)) << 7;
    const int acpar = grp >> 1;
    const int bcpar = grp & 1;

    float acc[4][4][4];
#pragma unroll
    for (int mt = 0; mt < 4; mt++)
#pragma unroll
        for (int nt = 0; nt < 4; nt++)
#pragma unroll
            for (int i = 0; i < 4; i++) acc[mt][nt][i] = 0.f;

    auto issue = [&](int kt, int stage) {
        const int k0 = kt * BKH;
        uint32_t dA = sbase + stage * STG;
        uint32_t dB = dA + ABYTES;
#pragma unroll
        for (int i = 0; i < 4; i++) {
            int idx = t + 256 * i;
            int row = idx >> 3;
            int c4  = idx & 7;
            uint32_t sw = ((uint32_t)row << 7) + ((uint32_t)(c4 ^ (row & 7)) << 4);
            int gm = bm + row;
            const __half* srcA = A + (size_t)(gm < M ? gm : 0) * D_ + k0 + c4 * 8;
            CP_ASYNC(dA + sw, srcA, (gm < M) ? 16 : 0);
            const __half* srcB = W + (size_t)(bn + row) * D_ + k0 + c4 * 8;
            CP_ASYNC(dB + sw, srcB, 16);
        }
        CP_COMMIT();
    };

    issue(0, 0);
    for (int kt = 0; kt < NKT; kt++) {
        const int buf = kt & 1;
        if (kt + 1 < NKT) { issue(kt + 1, buf ^ 1); CP_WAIT1(); }
        else              { CP_WAIT0(); }
        __syncthreads();

        const uint32_t sA = sbase + buf * STG;
        const uint32_t sB = sA + ABYTES;

#pragma unroll
        for (int ks = 0; ks < 4; ks++) {
            const uint32_t aco = (uint32_t)(((2 * ks + acpar) ^ lr) << 4);
            const uint32_t bco = (uint32_t)(((2 * ks + bcpar) ^ lr) << 4);

            uint32_t af[4][4];
#pragma unroll
            for (int mt = 0; mt < 4; mt++)
                ldsm_x4(af[mt], sA + aoff[mt] + aco);

            uint32_t bf[4][2];
#pragma unroll
            for (int np = 0; np < 2; np++) {
                uint32_t r[4];
                ldsm_x4(r, sB + boff[np] + bco);
                bf[2 * np][0]     = r[0];
                bf[2 * np][1]     = r[1];
                bf[2 * np + 1][0] = r[2];
                bf[2 * np + 1][1] = r[3];
            }
#pragma unroll
            for (int mt = 0; mt < 4; mt++)
#pragma unroll
                for (int nt = 0; nt < 4; nt++)
                    mma_f16(acc[mt][nt], af[mt], bf[nt]);
        }
        __syncthreads();
    }

#pragma unroll
    for (int nt = 0; nt < 4; nt++) {
        int c = bn + warpN * 32 + nt * 8 + tc * 2;
#pragma unroll
        for (int mt = 0; mt < 4; mt++) {
            int r0 = bm + warpM * 64 + mt * 16 + g;
            epilogue(r0,     c, acc[mt][nt][0], acc[mt][nt][1]);
            epilogue(r0 + 8, c, acc[mt][nt][2], acc[mt][nt][3]);
        }
    }
}

// ---------------------------------------------------------------------------
// Fused QKV GEMM + bias + rope (Q scaled). grid.x = 3*NBN.
// ---------------------------------------------------------------------------
__global__ __launch_bounds__(256, 2) void gemm_qkv_kernel(
    const __half* __restrict__ A, const __half* __restrict__ Wall,
    const float* __restrict__ bq, const float* __restrict__ bk,
    const float* __restrict__ bv, __half* __restrict__ Qh,
    __half* __restrict__ Kh, __half* __restrict__ Vh, int M)
{
    extern __shared__ __align__(128) char sm[];
    const int which = blockIdx.x / NBN;
    const int bn = (blockIdx.x % NBN) * BN;
    const int bm = blockIdx.y * BM;

    const __half* W = Wall + (size_t)which * D_ * D_;
    EpiQKV epi;
    epi.bias  = (which == 0) ? bq : (which == 1) ? bk : bv;
    epi.C     = (which == 0) ? Qh : (which == 1) ? Kh : Vh;
    epi.which = which;
    epi.M     = M;

    gemm_body(A, W, sm, bm, bn, M, epi);
}

// ---------------------------------------------------------------------------
// Plain GEMM + bias, fp32 output (final projection)
// ---------------------------------------------------------------------------
__global__ __launch_bounds__(256, 2) void gemm_out_kernel(
    const __half* __restrict__ A, const __half* __restrict__ W,
    const float* __restrict__ bias, float* __restrict__ C, int M)
{
    extern __shared__ __align__(128) char sm[];
    const int bn = blockIdx.x * BN;
    const int bm = blockIdx.y * BM;

    EpiOut epi; epi.bias = bias; epi.C = C; epi.M = M;
    gemm_body(A, W, sm, bm, bn, M, epi);
}

// ---------------------------------------------------------------------------
// Fused flash attention: ldmatrix feeds everywhere (Q per-tile A-frags,
// K non-trans, V trans), 3-buffer K/V rotation, one barrier per tile,
// __launch_bounds__(256,3) for 3 CTAs/SM occupancy.
// ---------------------------------------------------------------------------
#define QT   128
#define KT   32
#define QSTR 104                                  // halfs/row: 208B, 16B-aligned
constexpr int QS_HALFS   = QT * QSTR;             // 13312
constexpr int KBUF_HALFS = KT * QSTR;             // 3328
constexpr int VBUF_HALFS = KT * QSTR;             // 3328 (row-major V)
constexpr int BUF_HALFS  = KBUF_HALFS + VBUF_HALFS;
constexpr int ATT_SMEM   = (QS_HALFS + 3 * BUF_HALFS) * 2;   // 66560 bytes

__global__ __launch_bounds__(256, 3) void attn_mma_kernel(
    const __half* __restrict__ Q, const __half* __restrict__ K,
    const __half* __restrict__ V, __half* __restrict__ O)
{
    extern __shared__ __align__(16) __half smha[];
    __half* Qs = smha;
    const uint32_t smbase = smem_u32(smha);

    const int qt = blockIdx.x, h = blockIdx.y, b = blockIdx.z;
    const int q0 = qt * QT;
    const int t = threadIdx.x, lane = t & 31, wid = t >> 5;
    const int g = lane >> 2, tc = lane & 3;
    const int lr = lane & 7, grp = lane >> 3;

    // ---- stage Q tile (zero-padded cols 88..95) ----
    for (int idx = t; idx < QT * 24; idx += 256) {
        int r = idx / 24, c = idx % 24;
        int s = q0 + r; if (s >= SEQ_) s = SEQ_ - 1;
        uint2 v = make_uint2(0u, 0u);
        if (c < 22)
            v = *(const uint2*)&Q[(((size_t)b * SEQ_ + s) * H_ + h) * HD_ + c * 4];
        *(uint2*)&Qs[r * QSTR + c * 4] = v;
    }

    const int rw = wid * 16;
    // Q A-fragment ldsm base (per-tile reload; frees 24 registers)
    const uint32_t qrow = smbase +
        (uint32_t)(rw + lr + ((grp & 1) << 3)) * (QSTR * 2);
    const uint32_t qcpar = (uint32_t)(grp >> 1);

    // K (non-trans) ldsm bases
    uint32_t koff[2];
#pragma unroll
    for (int np = 0; np < 2; np++)
        koff[np] = (uint32_t)(np * 16 + lr + ((grp >> 1) << 3)) * (QSTR * 2);
    const uint32_t kcpar = (uint32_t)(grp & 1);
    // V (trans) ldsm bases
    const uint32_t vrow = (uint32_t)(((grp & 1) << 3) + lr) * (QSTR * 2);
    const uint32_t vcpar = (uint32_t)(grp >> 1);

    float oacc[11][4];
#pragma unroll
    for (int nt = 0; nt < 11; nt++)
#pragma unroll
        for (int i = 0; i < 4; i++) oacc[nt][i] = 0.f;
    float m0 = -1e30f, m1 = -1e30f, l0 = 0.f, l1 = 0.f;

    auto stage = [&](int k0, int bi) {
        __half* Ks = smha + QS_HALFS + bi * BUF_HALFS;
        __half* Vs = Ks + KBUF_HALFS;
        for (int idx = t; idx < KT * 24; idx += 256) {
            int r = idx / 24, c = idx % 24;
            int s = k0 + r;
            uint2 kv = make_uint2(0u, 0u), vv = make_uint2(0u, 0u);
            if (s < SEQ_ && c < 22) {
                size_t gg = (((size_t)b * SEQ_ + s) * H_ + h) * HD_ + c * 4;
                kv = *(const uint2*)&K[gg];
                vv = *(const uint2*)&V[gg];
            }
            *(uint2*)&Ks[r * QSTR + c * 4] = kv;
            *(uint2*)&Vs[r * QSTR + c * 4] = vv;
        }
    };

    constexpr int NT_ = (SEQ_ + KT - 1) / KT;   // 19
    stage(0, 0);

    for (int kt = 0; kt < NT_; kt++) {
        const int k0 = kt * KT;
        if (kt + 1 < NT_) stage(k0 + KT, (kt + 1) % 3);
        __syncthreads();

        const uint32_t sK = smbase + (QS_HALFS + (kt % 3) * BUF_HALFS) * 2;
        const uint32_t sV = sK + KBUF_HALFS * 2;

        // ---- scores S(16x32) per warp ----
        float sc[4][4];
#pragma unroll
        for (int nt = 0; nt < 4; nt++)
#pragma unroll
            for (int i = 0; i < 4; i++) sc[nt][i] = 0.f;

#pragma unroll
        for (int ks = 0; ks < 6; ks++) {
            uint32_t qf[4];
            ldsm_x4(qf, qrow + (2 * ks + qcpar) * 16);
            uint32_t bf[4][2];
#pragma unroll
            for (int np = 0; np < 2; np++) {
                uint32_t r[4];
                ldsm_x4(r, sK + koff[np] + (2 * ks + kcpar) * 16);
                bf[2 * np][0]     = r[0];
                bf[2 * np][1]     = r[1];
                bf[2 * np + 1][0] = r[2];
                bf[2 * np + 1][1] = r[3];
            }
#pragma unroll
            for (int nt = 0; nt < 4; nt++)
                mma_f16(sc[nt], qf, bf[nt]);
        }

        if (k0 + KT > SEQ_) {
#pragma unroll
            for (int nt = 0; nt < 4; nt++) {
                int kidx = k0 + nt * 8 + 2 * tc;
                if (kidx >= SEQ_)     { sc[nt][0] = -1e30f; sc[nt][2] = -1e30f; }
                if (kidx + 1 >= SEQ_) { sc[nt][1] = -1e30f; sc[nt][3] = -1e30f; }
            }
        }

        // ---- online softmax (warp-local) ----
        float mx0 = sc[0][0], mx1 = sc[0][2];
#pragma unroll
        for (int nt = 0; nt < 4; nt++) {
            mx0 = fmaxf(mx0, fmaxf(sc[nt][0], sc[nt][1]));
            mx1 = fmaxf(mx1, fmaxf(sc[nt][2], sc[nt][3]));
        }
        mx0 = fmaxf(mx0, __shfl_xor_sync(0xffffffffu, mx0, 1));
        mx0 = fmaxf(mx0, __shfl_xor_sync(0xffffffffu, mx0, 2));
        mx1 = fmaxf(mx1, __shfl_xor_sync(0xffffffffu, mx1, 1));
        mx1 = fmaxf(mx1, __shfl_xor_sync(0xffffffffu, mx1, 2));
        mx0 = fmaxf(mx0, m0); mx1 = fmaxf(mx1, m1);
        float corr0 = __expf(m0 - mx0), corr1 = __expf(m1 - mx1);
        m0 = mx0; m1 = mx1;

        float s0 = 0.f, s1 = 0.f;
#pragma unroll
        for (int nt = 0; nt < 4; nt++) {
            sc[nt][0] = __expf(sc[nt][0] - m0);
            sc[nt][1] = __expf(sc[nt][1] - m0);
            sc[nt][2] = __expf(sc[nt][2] - m1);
            sc[nt][3] = __expf(sc[nt][3] - m1);
            s0 += sc[nt][0] + sc[nt][1];
            s1 += sc[nt][2] + sc[nt][3];
        }
        s0 += __shfl_xor_sync(0xffffffffu, s0, 1);
        s0 += __shfl_xor_sync(0xffffffffu, s0, 2);
        s1 += __shfl_xor_sync(0xffffffffu, s1, 1);
        s1 += __shfl_xor_sync(0xffffffffu, s1, 2);
        l0 = l0 * corr0 + s0;
        l1 = l1 * corr1 + s1;

#pragma unroll
        for (int nt = 0; nt < 11; nt++) {
            oacc[nt][0] *= corr0; oacc[nt][1] *= corr0;
            oacc[nt][2] *= corr1; oacc[nt][3] *= corr1;
        }

        uint32_t pf[2][4];
#pragma unroll
        for (int kv = 0; kv < 2; kv++) {
            pf[kv][0] = packh2(sc[2 * kv][0],     sc[2 * kv][1]);
            pf[kv][1] = packh2(sc[2 * kv][2],     sc[2 * kv][3]);
            pf[kv][2] = packh2(sc[2 * kv + 1][0], sc[2 * kv + 1][1]);
            pf[kv][3] = packh2(sc[2 * kv + 1][2], sc[2 * kv + 1][3]);
        }

        // ---- PV: trans-ldmatrix V fragments from row-major Vs ----
#pragma unroll
        for (int kv = 0; kv < 2; kv++) {
            uint32_t vb = sV + (uint32_t)(kv * 16) * (QSTR * 2) + vrow;
            uint32_t bf[11][2];
#pragma unroll
            for (int npv = 0; npv < 5; npv++) {
                uint32_t r[4];
                ldsm_x4_t(r, vb + (npv * 2 + vcpar) * 16);
                bf[2 * npv][0]     = r[0];
                bf[2 * npv][1]     = r[1];
                bf[2 * npv + 1][0] = r[2];
                bf[2 * npv + 1][1] = r[3];
            }
            {
                uint32_t r[2];
                uint32_t addr = sV + (uint32_t)(kv * 16 + ((lane >> 3) & 1) * 8 + lr) * (QSTR * 2)
                              + 10 * 16;
                ldsm_x2_t(r, addr);
                bf[10][0] = r[0];
                bf[10][1] = r[1];
            }
#pragma unroll
            for (int nt = 0; nt < 11; nt++)
                mma_f16(oacc[nt], pf[kv], bf[nt]);
        }
    }

    float inv0 = 1.f / l0, inv1 = 1.f / l1;
    int s0 = q0 + rw + g, s1 = s0 + 8;
#pragma unroll
    for (int nt = 0; nt < 11; nt++) {
        int d = nt * 8 + 2 * tc;
        if (s0 < SEQ_)
            *(__half2*)&O[(((size_t)b * SEQ_ + s0) * H_ + h) * HD_ + d] =
                __floats2half2_rn(oacc[nt][0] * inv0, oacc[nt][1] * inv0);
        if (s1 < SEQ_)
            *(__half2*)&O[(((size_t)b * SEQ_ + s1) * H_ + h) * HD_ + d] =
                __floats2half2_rn(oacc[nt][2] * inv1, oacc[nt][3] * inv1);
    }
}

// ---------------------------------------------------------------------------
extern "C" void kernel_launch(void* const* d_in, const int* in_sizes, int n_in,
                              void* d_out, int out_size)
{
    const float* X  = (const float*)d_in[0];
    const float* wq = (const float*)d_in[1];
    const float* bq = (const float*)d_in[2];
    const float* wk = (const float*)d_in[3];
    const float* bk = (const float*)d_in[4];
    const float* wv = (const float*)d_in[5];
    const float* bv = (const float*)d_in[6];
    const float* wo = (const float*)d_in[7];
    const float* bo = (const float*)d_in[8];
    float* out = (float*)d_out;

    __half *Qh, *Kh, *Vh, *Xh, *Wh;
    cudaGetSymbolAddress((void**)&Qh, g_Qh);
    cudaGetSymbolAddress((void**)&Kh, g_Kh);
    cudaGetSymbolAddress((void**)&Vh, g_Vh);
    cudaGetSymbolAddress((void**)&Xh, g_Xh);
    cudaGetSymbolAddress((void**)&Wh, g_Wh);

    cudaFuncSetAttribute(gemm_qkv_kernel,
                         cudaFuncAttributeMaxDynamicSharedMemorySize, GSMEM);
    cudaFuncSetAttribute(gemm_out_kernel,
                         cudaFuncAttributeMaxDynamicSharedMemorySize, GSMEM);
    cudaFuncSetAttribute(attn_mma_kernel,
                         cudaFuncAttributeMaxDynamicSharedMemorySize, ATT_SMEM);

    const int WN4 = D_ * D_ / 4;
    const int XN4 = M_ * D_ / 4;
    f2h_kernel<<<(XN4 + 255) / 256, 256>>>(X, Xh, XN4);
    dim3 wgrid((WN4 + 255) / 256, 4);
    f2h4_kernel<<<wgrid, 256>>>(wq, wk, wv, wo, Wh, WN4);
    rope_init_kernel<<<(SEQ_ * 44 + 255) / 256, 256>>>();

    dim3 qgrid(3 * NBN, (M_ + BM - 1) / BM);   // (33, 145)
    gemm_qkv_kernel<<<qgrid, 256, GSMEM>>>(Xh, Wh, bq, bk, bv, Qh, Kh, Vh, M_);

    dim3 agrid((SEQ_ + QT - 1) / QT, H_, B_);  // (5, 16, 32)
    attn_mma_kernel<<<agrid, 256, ATT_SMEM>>>(Qh, Kh, Vh, Xh);

    dim3 ogrid(NBN, (M_ + BM - 1) / BM);       // (11, 145)
    gemm_out_kernel<<<ogrid, 256, GSMEM>>>(Xh, Wh + 3 * (size_t)D_ * D_, bo, out, M_);
}